// round 5
// baseline (speedup 1.0000x reference)
#include <cuda_runtime.h>
#include <cuda_bf16.h>
#include <math.h>
#include <stdint.h>

#define NND    6144
#define NFEAT  512
#define NHID   256
#define NCLASS 8
#define ADIM   128

typedef __nv_bfloat16 bf16;

// ---------------- device scratch (no allocations allowed) ----------------
__device__ float g_zcat[NND * 384];
__device__ float g_nzT[3 * NND];
__device__ float g_adj[(size_t)NND * NND];      // fp32 (needed by L7 mul + final)
__device__ float g_att[(size_t)NND * NND];      // fp32 raw logits (softmax input)
__device__ float g_xt[(size_t)NND * NHID];
__device__ float g_xtw2[NND * NCLASS];

// bf16 hi/lo split operands
__device__ bf16 g_WaTH[3][(size_t)ADIM * NND], g_WaTL[3][(size_t)ADIM * NND];
__device__ bf16 g_W1TH[NHID * NFEAT],          g_W1TL[NHID * NFEAT];
__device__ bf16 g_WqTH[NHID * NHID], g_WqTL[NHID * NHID];
__device__ bf16 g_WkTH[NHID * NHID], g_WkTL[NHID * NHID];
__device__ bf16 g_WvTH[NHID * NHID], g_WvTL[NHID * NHID];
__device__ bf16 g_featsH[(size_t)NND * NFEAT], g_featsL[(size_t)NND * NFEAT];
__device__ bf16 g_adjH[(size_t)NND * NND],     g_adjL[(size_t)NND * NND];
__device__ bf16 g_fW1TH[(size_t)NHID * NND],   g_fW1TL[(size_t)NHID * NND];
__device__ bf16 g_xH[(size_t)NND * NHID],      g_xL[(size_t)NND * NHID];
__device__ bf16 g_QH[(size_t)NND * NHID],      g_QL[(size_t)NND * NHID];
__device__ bf16 g_KH[(size_t)NND * NHID],      g_KL[(size_t)NND * NHID];
__device__ bf16 g_VTH[(size_t)NHID * NND],     g_VTL[(size_t)NHID * NND];
__device__ bf16 g_attH[(size_t)NND * NND],     g_attL[(size_t)NND * NND];

// ---------------- helpers ----------------
__device__ __forceinline__ uint32_t s2u(const void* p) {
    uint32_t a;
    asm("{ .reg .u64 t; cvta.to.shared.u64 t, %1; cvt.u32.u64 %0, t; }" : "=r"(a) : "l"(p));
    return a;
}
__device__ __forceinline__ void split1(float v, bf16& h, bf16& l) {
    h = __float2bfloat16(v);
    l = __float2bfloat16(v - __bfloat162float(h));
}
// split (x,y) -> packed bf16x2 hi, packed bf16x2 lo
__device__ __forceinline__ void cvt_split2(float x, float y, uint32_t& hi, uint32_t& lo) {
    __nv_bfloat162 h = __float22bfloat162_rn(make_float2(x, y));
    hi = *reinterpret_cast<uint32_t*>(&h);
    float hx = __uint_as_float(hi << 16);
    float hy = __uint_as_float(hi & 0xFFFF0000u);
    __nv_bfloat162 l = __float22bfloat162_rn(make_float2(x - hx, y - hy));
    lo = *reinterpret_cast<uint32_t*>(&l);
}
__device__ __forceinline__ void split4(float4 v, uint2& h, uint2& l) {
    cvt_split2(v.x, v.y, h.x, l.x);
    cvt_split2(v.z, v.w, h.y, l.y);
}

#define LDSM4(r, a)                                                                        \
    asm volatile("ldmatrix.sync.aligned.m8n8.x4.shared.b16 {%0,%1,%2,%3}, [%4];"           \
                 : "=r"((r)[0]), "=r"((r)[1]), "=r"((r)[2]), "=r"((r)[3]) : "r"(a))
#define LDSM2(r, a)                                                                        \
    asm volatile("ldmatrix.sync.aligned.m8n8.x2.shared.b16 {%0,%1}, [%2];"                 \
                 : "=r"((r)[0]), "=r"((r)[1]) : "r"(a))

__device__ __forceinline__ void mma16816(float c[4], const uint32_t a[4], const uint32_t b[2]) {
    asm volatile(
        "mma.sync.aligned.m16n8k16.row.col.f32.bf16.bf16.f32 "
        "{%0,%1,%2,%3}, {%4,%5,%6,%7}, {%8,%9}, {%0,%1,%2,%3};"
        : "+f"(c[0]), "+f"(c[1]), "+f"(c[2]), "+f"(c[3])
        : "r"(a[0]), "r"(a[1]), "r"(a[2]), "r"(a[3]), "r"(b[0]), "r"(b[1]));
}
#define CP_COMMIT() asm volatile("cp.async.commit_group;" ::: "memory")

// ---------------- GEMM: C = act((A @ B'^T) * mul + bias) ----------------
// A: [M,K]: either fp32 (aCvt) or bf16 hi/lo pair. B': [N,K] bf16 hi/lo.
// CTA tile 128x128, 8 warps, warp tile 64x32, KC=32/iter.
// 3-term split: Ah*Bh + Ah*Bl + Al*Bh, fp32 accum.
struct GArgs {
    const float* Af[3];                   // fp32 A (aCvt mode)
    const bf16* AH[3]; const bf16* AL[3]; // bf16 A (cp.async mode)
    const bf16* BH[3]; const bf16* BL[3];
    float* C[3];                          // estore 0
    bf16* CH[3]; bf16* CL[3];             // estore 2/3
    const float* bias[3];
    const float* mul;
    int M, N, K, lda, ldb, ldc, act, aCvt;
    int estore[3];                        // 0 fp32, 2 split, 3 split transposed
};

#define ROWB 80
#define TILEB (128 * ROWB)
#define STAGEB (4 * TILEB)
#define GSMEM (2 * STAGEB)

__global__ void __launch_bounds__(256, 1) mma_gemm(const GArgs p) {
    extern __shared__ __align__(16) char smem[];

    const int bz = blockIdx.z;
    const float* __restrict__ Af  = p.Af[bz];
    const bf16* __restrict__ pAH  = p.AH[bz];
    const bf16* __restrict__ pAL  = p.AL[bz];
    const bf16* __restrict__ pBH  = p.BH[bz];
    const bf16* __restrict__ pBL  = p.BL[bz];
    const float* __restrict__ bias = p.bias[bz];

    const int m0 = blockIdx.x * 128, n0 = blockIdx.y * 128;
    const int lda = p.lda, ldb = p.ldb, ldc = p.ldc, K = p.K;
    const int aCvt = p.aCvt;

    const int tid  = threadIdx.x;
    const int lane = tid & 31, wid = tid >> 5;
    const int wm = wid & 1, wn = wid >> 1;

    const uint32_t u0 = s2u(smem);
    const uint32_t aRowOff = (uint32_t)((lane & 15) * ROWB + ((lane & 16) ? 16 : 0));
    const uint32_t bRowOff = (uint32_t)((lane & 7) * ROWB + ((lane & 8) ? 16 : 0));

    float acc[4][4][4];
#pragma unroll
    for (int mt = 0; mt < 4; mt++)
#pragma unroll
        for (int nt = 0; nt < 4; nt++)
#pragma unroll
            for (int q = 0; q < 4; q++) acc[mt][nt][q] = 0.f;

    float4 ra[4];

    // 16B cp.async of one 128x32 bf16 tile (rowOff = tile base row in src)
    auto cpTile = [&](uint32_t dstBase, const bf16* src, int ld, int rowOff, int k0) {
#pragma unroll
        for (int j = 0; j < 2; j++) {
            int chunk = tid + j * 256;
            int row = chunk >> 2;
            uint32_t dst = dstBase + (uint32_t)(row * ROWB + ((chunk & 3) << 4));
            const bf16* s = src + (size_t)(rowOff + row) * ld + k0 + ((chunk & 3) << 3);
            asm volatile("cp.async.cg.shared.global [%0], [%1], 16;" :: "r"(dst), "l"(s)
                         : "memory");
        }
    };
    auto cpFill = [&](int stage, int k0) {
        uint32_t sb = u0 + (uint32_t)(stage * STAGEB);
        if (!aCvt) {
            cpTile(sb, pAH, lda, m0, k0);
            cpTile(sb + TILEB, pAL, lda, m0, k0);
        }
        cpTile(sb + 2 * TILEB, pBH, ldb, n0, k0);
        cpTile(sb + 3 * TILEB, pBL, ldb, n0, k0);
    };
    auto loadA = [&](int k0) {
#pragma unroll
        for (int l = 0; l < 4; l++) {
            int idx = tid + l * 256;
            int row = idx >> 3;
            int c4  = (idx & 7) << 2;
            ra[l] = *reinterpret_cast<const float4*>(Af + (size_t)(m0 + row) * lda + k0 + c4);
        }
    };
    auto storeA = [&](int stage) {
        char* AHp = smem + stage * STAGEB;
        char* ALp = AHp + TILEB;
#pragma unroll
        for (int l = 0; l < 4; l++) {
            int idx = tid + l * 256;
            int row = idx >> 3;
            int off = row * ROWB + ((idx & 7) << 3);
            uint2 h, lo;
            split4(ra[l], h, lo);
            *reinterpret_cast<uint2*>(AHp + off) = h;
            *reinterpret_cast<uint2*>(ALp + off) = lo;
        }
    };
    auto compute = [&](int stage) {
        const uint32_t uAH = u0 + (uint32_t)(stage * STAGEB);
        const uint32_t uAL = uAH + TILEB;
        const uint32_t uBH = uAL + TILEB;
        const uint32_t uBL = uBH + TILEB;
#pragma unroll
        for (int pass = 0; pass < 3; pass++) {
            const uint32_t aBase = (pass < 2) ? uAH : uAL;
            const uint32_t bBase = (pass == 1) ? uBL : uBH;
#pragma unroll
            for (int ks = 0; ks < 2; ks++) {
                uint32_t af[4][4], bf_[4][2];
#pragma unroll
                for (int mt = 0; mt < 4; mt++)
                    LDSM4(af[mt], aBase + (uint32_t)((wm * 64 + mt * 16) * ROWB) + aRowOff +
                                      (uint32_t)(ks * 32));
#pragma unroll
                for (int nt = 0; nt < 4; nt++)
                    LDSM2(bf_[nt], bBase + (uint32_t)((wn * 32 + nt * 8) * ROWB) + bRowOff +
                                       (uint32_t)(ks * 32));
#pragma unroll
                for (int mt = 0; mt < 4; mt++)
#pragma unroll
                    for (int nt = 0; nt < 4; nt++) mma16816(acc[mt][nt], af[mt], bf_[nt]);
            }
        }
    };

    const int niter = K >> 5;
    if (aCvt) {
        loadA(0);
        storeA(0);
        if (niter > 1) loadA(32);
    }
    cpFill(0, 0);
    CP_COMMIT();
    if (niter > 1) {
        cpFill(1, 32);
        CP_COMMIT();
    }
    for (int i = 0; i < niter; i++) {
        if (i + 1 < niter) asm volatile("cp.async.wait_group 1;" ::: "memory");
        else               asm volatile("cp.async.wait_group 0;" ::: "memory");
        __syncthreads();
        compute(i & 1);
        __syncthreads();
        if (aCvt) {
            if (i + 1 < niter) storeA((i + 1) & 1);
            if (i + 2 < niter) loadA((i + 2) << 5);
        }
        if (i + 2 < niter) {
            cpFill(i & 1, (i + 2) << 5);
            CP_COMMIT();
        }
    }

    // ---------------- epilogue ----------------
    const int es = p.estore[bz];
    float* __restrict__       C  = p.C[bz];
    bf16* __restrict__        CH = p.CH[bz];
    bf16* __restrict__        CL = p.CL[bz];
    const float* __restrict__ mul = p.mul;
#pragma unroll
    for (int mt = 0; mt < 4; mt++) {
#pragma unroll
        for (int nt = 0; nt < 4; nt++) {
            int mA = m0 + wm * 64 + mt * 16 + (lane >> 2);
            int n  = n0 + wn * 32 + nt * 8 + 2 * (lane & 3);
#pragma unroll
            for (int h = 0; h < 2; h++) {
                int mm = mA + h * 8;
                float vx = acc[mt][nt][2 * h + 0];
                float vy = acc[mt][nt][2 * h + 1];
                if (mul) {
                    float2 mv = *reinterpret_cast<const float2*>(&mul[(size_t)mm * ldc + n]);
                    vx *= mv.x; vy *= mv.y;
                }
                if (bias) { vx += bias[n]; vy += bias[n + 1]; }
                if (p.act) { vx = fmaxf(vx, 0.f); vy = fmaxf(vy, 0.f); }
                if (es == 0) {
                    *reinterpret_cast<float2*>(&C[(size_t)mm * ldc + n]) = make_float2(vx, vy);
                } else if (es == 2) {
                    uint32_t hi, lo;
                    cvt_split2(vx, vy, hi, lo);
                    *reinterpret_cast<uint32_t*>(&CH[(size_t)mm * ldc + n]) = hi;
                    *reinterpret_cast<uint32_t*>(&CL[(size_t)mm * ldc + n]) = lo;
                } else {  // 3: transposed split
                    bf16 hx, lx, hy, ly;
                    split1(vx, hx, lx);
                    split1(vy, hy, ly);
                    CH[(size_t)n * p.M + mm] = hx;
                    CL[(size_t)n * p.M + mm] = lx;
                    CH[(size_t)(n + 1) * p.M + mm] = hy;
                    CL[(size_t)(n + 1) * p.M + mm] = ly;
                }
            }
        }
    }
}

// ---------------- transpose + split: out[c][r] = split(in[r][c]) ----------------
struct TSArgs {
    const float* in[3];
    bf16* oH[3]; bf16* oL[3];
    int R, C;
};
__global__ void transpose_split_k(const TSArgs p) {
    __shared__ float t[32][33];
    const float* __restrict__ in = p.in[blockIdx.z];
    bf16* __restrict__ oH = p.oH[blockIdx.z];
    bf16* __restrict__ oL = p.oL[blockIdx.z];
    const int R = p.R, C = p.C;
    int c0 = blockIdx.x * 32, r0 = blockIdx.y * 32;
    int x = threadIdx.x, y = threadIdx.y;
#pragma unroll
    for (int i = 0; i < 32; i += 8) t[y + i][x] = in[(size_t)(r0 + y + i) * C + c0 + x];
    __syncthreads();
#pragma unroll
    for (int i = 0; i < 32; i += 8) {
        float v = t[x][y + i];
        bf16 h, l;
        split1(v, h, l);
        oH[(size_t)(c0 + y + i) * R + r0 + x] = h;
        oL[(size_t)(c0 + y + i) * R + r0 + x] = l;
    }
}

// ---------------- elementwise split (feats) ----------------
__global__ void split_k(const float* __restrict__ in, bf16* __restrict__ oH,
                        bf16* __restrict__ oL, int n4) {
    for (int e = blockIdx.x * blockDim.x + threadIdx.x; e < n4; e += gridDim.x * blockDim.x) {
        float4 v = reinterpret_cast<const float4*>(in)[e];
        uint2 h, l;
        split4(v, h, l);
        reinterpret_cast<uint2*>(oH)[e] = h;
        reinterpret_cast<uint2*>(oL)[e] = l;
    }
}

// ---------------- gate: z4 = zcat @ Wagg + bagg ; nz = softmax(z4) ----------------
__global__ void agg_softmax_k(const float* __restrict__ Wagg, const float* __restrict__ bagg,
                              float* __restrict__ out_nz, int write_out) {
    int row  = blockIdx.x * (blockDim.x / 32) + (threadIdx.x >> 5);
    int lane = threadIdx.x & 31;
    if (row >= NND) return;
    const float* z = &g_zcat[(size_t)row * 384];
    float s0 = 0.f, s1 = 0.f, s2 = 0.f;
    for (int k = lane; k < 384; k += 32) {
        float v = z[k];
        s0 = fmaf(v, Wagg[k * 3 + 0], s0);
        s1 = fmaf(v, Wagg[k * 3 + 1], s1);
        s2 = fmaf(v, Wagg[k * 3 + 2], s2);
    }
#pragma unroll
    for (int off = 16; off; off >>= 1) {
        s0 += __shfl_down_sync(0xffffffffu, s0, off);
        s1 += __shfl_down_sync(0xffffffffu, s1, off);
        s2 += __shfl_down_sync(0xffffffffu, s2, off);
    }
    if (lane == 0) {
        s0 += bagg[0]; s1 += bagg[1]; s2 += bagg[2];
        float mx = fmaxf(s0, fmaxf(s1, s2));
        float e0 = expf(s0 - mx), e1 = expf(s1 - mx), e2 = expf(s2 - mx);
        float inv = 1.f / (e0 + e1 + e2);
        e0 *= inv; e1 *= inv; e2 *= inv;
        g_nzT[0 * NND + row] = e0;
        g_nzT[1 * NND + row] = e1;
        g_nzT[2 * NND + row] = e2;
        if (write_out) {
            out_nz[row * 3 + 0] = e0;
            out_nz[row * 3 + 1] = e1;
            out_nz[row * 3 + 2] = e2;
        }
    }
}

// ---- adj[i,j] = nz[j,0]*a0 + nz[j,1]*a1 + nz[j,2]*a2 ; also emit bf16 split ----
__global__ void build_adj_k(const float* __restrict__ a0, const float* __restrict__ a1,
                            const float* __restrict__ a2) {
    const size_t total4 = (size_t)NND * NND / 4;
    for (size_t e = (size_t)blockIdx.x * blockDim.x + threadIdx.x; e < total4;
         e += (size_t)gridDim.x * blockDim.x) {
        size_t off = e * 4;
        int j = (int)(off % NND);
        float4 w0 = *reinterpret_cast<const float4*>(&g_nzT[j]);
        float4 w1 = *reinterpret_cast<const float4*>(&g_nzT[NND + j]);
        float4 w2 = *reinterpret_cast<const float4*>(&g_nzT[2 * NND + j]);
        float4 x0 = *reinterpret_cast<const float4*>(a0 + off);
        float4 x1 = *reinterpret_cast<const float4*>(a1 + off);
        float4 x2 = *reinterpret_cast<const float4*>(a2 + off);
        float4 r;
        r.x = w0.x * x0.x + w1.x * x1.x + w2.x * x2.x;
        r.y = w0.y * x0.y + w1.y * x1.y + w2.y * x2.y;
        r.z = w0.z * x0.z + w1.z * x1.z + w2.z * x2.z;
        r.w = w0.w * x0.w + w1.w * x1.w + w2.w * x2.w;
        *reinterpret_cast<float4*>(&g_adj[off]) = r;
        uint2 h, l;
        split4(r, h, l);
        *reinterpret_cast<uint2*>(&g_adjH[off]) = h;
        *reinterpret_cast<uint2*>(&g_adjL[off]) = l;
    }
}

// ---- per-row softmax over 6144-wide logits; emit bf16 split of the result ----
__global__ void attn_softmax_k() {
    const int row = blockIdx.x;
    const float* __restrict__ ptr = &g_att[(size_t)row * NND];
    const int tid  = threadIdx.x;
    const int lane = tid & 31, warp = tid >> 5;
    float4 v[6];
    float mx = -3.4e38f;
#pragma unroll
    for (int l = 0; l < 6; l++) {
        v[l] = *reinterpret_cast<const float4*>(&ptr[(tid + l * 256) * 4]);
        mx = fmaxf(mx, fmaxf(fmaxf(v[l].x, v[l].y), fmaxf(v[l].z, v[l].w)));
    }
    __shared__ float sm[8], ss[8];
#pragma unroll
    for (int off = 16; off; off >>= 1) mx = fmaxf(mx, __shfl_xor_sync(0xffffffffu, mx, off));
    if (lane == 0) sm[warp] = mx;
    __syncthreads();
    float bm = fmaxf(fmaxf(fmaxf(sm[0], sm[1]), fmaxf(sm[2], sm[3])),
                     fmaxf(fmaxf(sm[4], sm[5]), fmaxf(sm[6], sm[7])));
    float sum = 0.f;
#pragma unroll
    for (int l = 0; l < 6; l++) {
        v[l].x = expf(v[l].x - bm);
        v[l].y = expf(v[l].y - bm);
        v[l].z = expf(v[l].z - bm);
        v[l].w = expf(v[l].w - bm);
        sum += v[l].x + v[l].y + v[l].z + v[l].w;
    }
#pragma unroll
    for (int off = 16; off; off >>= 1) sum += __shfl_xor_sync(0xffffffffu, sum, off);
    if (lane == 0) ss[warp] = sum;
    __syncthreads();
    float tot = ss[0] + ss[1] + ss[2] + ss[3] + ss[4] + ss[5] + ss[6] + ss[7];
    float scale = 1.f / tot;
#pragma unroll
    for (int l = 0; l < 6; l++) {
        v[l].x *= scale; v[l].y *= scale; v[l].z *= scale; v[l].w *= scale;
        uint2 h, lo;
        split4(v[l], h, lo);
        size_t off = (size_t)row * NND + (tid + l * 256) * 4;
        *reinterpret_cast<uint2*>(&g_attH[off]) = h;
        *reinterpret_cast<uint2*>(&g_attL[off]) = lo;
    }
}

// ---------------- X_tilde @ W2 (skinny, N=8) ----------------
__global__ void xtw2_k(const float* __restrict__ W2) {
    int row  = blockIdx.x * 8 + (threadIdx.x >> 5);
    int lane = threadIdx.x & 31;
    if (row >= NND) return;
    const float* xr = &g_xt[(size_t)row * NHID];
    float acc[8] = {0, 0, 0, 0, 0, 0, 0, 0};
    for (int h = lane; h < NHID; h += 32) {
        float xv = xr[h];
        const float4* wp = reinterpret_cast<const float4*>(&W2[h * 8]);
        float4 wlo = wp[0], whi = wp[1];
        acc[0] = fmaf(xv, wlo.x, acc[0]);
        acc[1] = fmaf(xv, wlo.y, acc[1]);
        acc[2] = fmaf(xv, wlo.z, acc[2]);
        acc[3] = fmaf(xv, wlo.w, acc[3]);
        acc[4] = fmaf(xv, whi.x, acc[4]);
        acc[5] = fmaf(xv, whi.y, acc[5]);
        acc[6] = fmaf(xv, whi.z, acc[6]);
        acc[7] = fmaf(xv, whi.w, acc[7]);
    }
#pragma unroll
    for (int c = 0; c < 8; c++)
#pragma unroll
        for (int off = 16; off; off >>= 1) acc[c] += __shfl_down_sync(0xffffffffu, acc[c], off);
    if (lane == 0) {
#pragma unroll
        for (int c = 0; c < 8; c++) g_xtw2[row * 8 + c] = acc[c];
    }
}

// ---------------- z = adj @ xtw2 + b2 ; out = softmax(z, axis=1). 8 rows/CTA ----
__global__ void final_k(const float* __restrict__ b2, float* __restrict__ out) {
    const int r0  = blockIdx.x * 8;
    const int tid = threadIdx.x;
    float acc[8][8];
#pragma unroll
    for (int r = 0; r < 8; r++)
#pragma unroll
        for (int c = 0; c < 8; c++) acc[r][c] = 0.f;

    for (int j4 = tid; j4 < NND / 4; j4 += 256) {
        float4 w[8];
        const float4* wp = reinterpret_cast<const float4*>(&g_xtw2[(size_t)j4 * 32]);
#pragma unroll
        for (int q = 0; q < 8; q++) w[q] = wp[q];
#pragma unroll
        for (int r = 0; r < 8; r++) {
            float4 a = *reinterpret_cast<const float4*>(&g_adj[(size_t)(r0 + r) * NND + j4 * 4]);
            float av[4] = {a.x, a.y, a.z, a.w};
#pragma unroll
            for (int q = 0; q < 4; q++) {
                acc[r][0] = fmaf(av[q], w[2 * q].x, acc[r][0]);
                acc[r][1] = fmaf(av[q], w[2 * q].y, acc[r][1]);
                acc[r][2] = fmaf(av[q], w[2 * q].z, acc[r][2]);
                acc[r][3] = fmaf(av[q], w[2 * q].w, acc[r][3]);
                acc[r][4] = fmaf(av[q], w[2 * q + 1].x, acc[r][4]);
                acc[r][5] = fmaf(av[q], w[2 * q + 1].y, acc[r][5]);
                acc[r][6] = fmaf(av[q], w[2 * q + 1].z, acc[r][6]);
                acc[r][7] = fmaf(av[q], w[2 * q + 1].w, acc[r][7]);
            }
        }
    }

    __shared__ float sred[8][64];
    const int lane = tid & 31, warp = tid >> 5;
#pragma unroll
    for (int r = 0; r < 8; r++)
#pragma unroll
        for (int c = 0; c < 8; c++) {
            float vv = acc[r][c];
#pragma unroll
            for (int off = 16; off; off >>= 1) vv += __shfl_down_sync(0xffffffffu, vv, off);
            if (lane == 0) sred[warp][r * 8 + c] = vv;
        }
    __syncthreads();
    if (tid < 64) {
        float v = 0.f;
#pragma unroll
        for (int w = 0; w < 8; w++) v += sred[w][tid];
        int c = tid & 7;
        v += b2[c];
        float mx = v;
#pragma unroll
        for (int off = 4; off; off >>= 1) mx = fmaxf(mx, __shfl_xor_sync(0xffffffffu, mx, off, 8));
        float e = expf(v - mx);
        float s = e;
#pragma unroll
        for (int off = 4; off; off >>= 1) s += __shfl_xor_sync(0xffffffffu, s, off, 8);
        out[(size_t)(r0 + (tid >> 3)) * 8 + c] = e / s;
    }
}

// ---------------- host side ----------------
template <typename T>
static T* symaddr(const void* sym) {
    void* p = nullptr;
    cudaGetSymbolAddress(&p, sym);
    return (T*)p;
}

extern "C" void kernel_launch(void* const* d_in, const int* in_sizes, int n_in,
                              void* d_out, int out_size) {
    const float* adj0 = (const float*)d_in[0];
    const float* adj1 = (const float*)d_in[1];
    const float* adj2 = (const float*)d_in[2];
    const float* feats = (const float*)d_in[3];
    const float* Wa1 = (const float*)d_in[4];
    const float* ba1 = (const float*)d_in[5];
    const float* Wa2 = (const float*)d_in[6];
    const float* ba2 = (const float*)d_in[7];
    const float* Wa3 = (const float*)d_in[8];
    const float* ba3 = (const float*)d_in[9];
    const float* Wagg = (const float*)d_in[10];
    const float* bagg = (const float*)d_in[11];
    const float* W1 = (const float*)d_in[12];
    const float* b1 = (const float*)d_in[13];
    const float* Wq = (const float*)d_in[14];
    const float* bq = (const float*)d_in[15];
    const float* Wk = (const float*)d_in[16];
    const float* bk = (const float*)d_in[17];
    const float* Wv = (const float*)d_in[18];
    const float* bv = (const float*)d_in[19];
    const float* W2 = (const float*)d_in[20];
    const float* b2 = (const float*)d_in[21];
    float* out = (float*)d_out;

    float* zcat  = symaddr<float>(g_zcat);
    float* adjp  = symaddr<float>(g_adj);
    float* attp  = symaddr<float>(g_att);
    float* xtp   = symaddr<float>(g_xt);
    bf16* WaTH = symaddr<bf16>(g_WaTH);  bf16* WaTL = symaddr<bf16>(g_WaTL);
    bf16* W1TH = symaddr<bf16>(g_W1TH);  bf16* W1TL = symaddr<bf16>(g_W1TL);
    bf16* WqTH = symaddr<bf16>(g_WqTH);  bf16* WqTL = symaddr<bf16>(g_WqTL);
    bf16* WkTH = symaddr<bf16>(g_WkTH);  bf16* WkTL = symaddr<bf16>(g_WkTL);
    bf16* WvTH = symaddr<bf16>(g_WvTH);  bf16* WvTL = symaddr<bf16>(g_WvTL);
    bf16* ftH  = symaddr<bf16>(g_featsH); bf16* ftL = symaddr<bf16>(g_featsL);
    bf16* adjH = symaddr<bf16>(g_adjH);  bf16* adjL = symaddr<bf16>(g_adjL);
    bf16* fW1TH = symaddr<bf16>(g_fW1TH); bf16* fW1TL = symaddr<bf16>(g_fW1TL);
    bf16* xH   = symaddr<bf16>(g_xH);    bf16* xL   = symaddr<bf16>(g_xL);
    bf16* QH   = symaddr<bf16>(g_QH);    bf16* QL   = symaddr<bf16>(g_QL);
    bf16* KHp  = symaddr<bf16>(g_KH);    bf16* KLp  = symaddr<bf16>(g_KL);
    bf16* VTH  = symaddr<bf16>(g_VTH);   bf16* VTL  = symaddr<bf16>(g_VTL);
    bf16* attH = symaddr<bf16>(g_attH);  bf16* attL = symaddr<bf16>(g_attL);

    cudaFuncSetAttribute(mma_gemm, cudaFuncAttributeMaxDynamicSharedMemorySize, GSMEM);

    const size_t WA = (size_t)ADIM * NND;

    // 0: Wa transposes (batched)
    {
        TSArgs t{};
        t.in[0] = Wa1; t.in[1] = Wa2; t.in[2] = Wa3;
        t.oH[0] = WaTH; t.oH[1] = WaTH + WA; t.oH[2] = WaTH + 2 * WA;
        t.oL[0] = WaTL; t.oL[1] = WaTL + WA; t.oL[2] = WaTL + 2 * WA;
        t.R = NND; t.C = ADIM;
        transpose_split_k<<<dim3(ADIM / 32, NND / 32, 3), dim3(32, 8)>>>(t);
    }
    // 1: W1 transpose
    {
        TSArgs t{};
        t.in[0] = W1; t.oH[0] = W1TH; t.oL[0] = W1TL; t.R = NFEAT; t.C = NHID;
        transpose_split_k<<<dim3(NHID / 32, NFEAT / 32, 1), dim3(32, 8)>>>(t);
    }
    // 2: Wq/Wk/Wv transposes (batched)
    {
        TSArgs t{};
        t.in[0] = Wq; t.in[1] = Wk; t.in[2] = Wv;
        t.oH[0] = WqTH; t.oH[1] = WkTH; t.oH[2] = WvTH;
        t.oL[0] = WqTL; t.oL[1] = WkTL; t.oL[2] = WvTL;
        t.R = NHID; t.C = NHID;
        transpose_split_k<<<dim3(NHID / 32, NHID / 32, 3), dim3(32, 8)>>>(t);
    }
    // 3: feats split
    split_k<<<592, 256>>>(feats, ftH, ftL, NND * NFEAT / 4);

    // 4: L1: z_i = adj_i @ Wa_i + ba_i  (aCvt A; cp.async B)
    {
        GArgs a{};
        a.Af[0] = adj0; a.Af[1] = adj1; a.Af[2] = adj2;
        a.BH[0] = WaTH; a.BH[1] = WaTH + WA; a.BH[2] = WaTH + 2 * WA;
        a.BL[0] = WaTL; a.BL[1] = WaTL + WA; a.BL[2] = WaTL + 2 * WA;
        a.C[0] = zcat; a.C[1] = zcat + ADIM; a.C[2] = zcat + 2 * ADIM;
        a.bias[0] = ba1; a.bias[1] = ba2; a.bias[2] = ba3;
        a.M = NND; a.N = ADIM; a.K = NND; a.lda = NND; a.ldb = NND; a.ldc = 384;
        a.aCvt = 1;
        mma_gemm<<<dim3(48, 1, 3), 256, GSMEM>>>(a);
    }

    // 5: L4: fW1^T(split) = (feats @ W1)^T   <-- ncu profiles this launch
    {
        GArgs a{};
        a.AH[0] = ftH; a.AL[0] = ftL;
        a.BH[0] = W1TH; a.BL[0] = W1TL;
        a.CH[0] = fW1TH; a.CL[0] = fW1TL;
        a.M = NND; a.N = NHID; a.K = NFEAT; a.lda = NFEAT; a.ldb = NFEAT; a.ldc = NHID;
        a.estore[0] = 3;
        mma_gemm<<<dim3(48, 2, 1), 256, GSMEM>>>(a);
    }

    // 6, 7
    int write_nz = (out_size >= NND * (NCLASS + 3)) ? 1 : 0;
    agg_softmax_k<<<768, 256>>>(Wagg, bagg, out + (size_t)NND * NCLASS, write_nz);
    build_adj_k<<<1184, 256>>>(adj0, adj1, adj2);

    // 8: L5: x(split) = relu(adj @ fW1 + b1)
    {
        GArgs a{};
        a.AH[0] = adjH; a.AL[0] = adjL;
        a.BH[0] = fW1TH; a.BL[0] = fW1TL;
        a.CH[0] = xH; a.CL[0] = xL;
        a.bias[0] = b1;
        a.M = NND; a.N = NHID; a.K = NND; a.lda = NND; a.ldb = NND; a.ldc = NHID;
        a.act = 1; a.estore[0] = 2;
        mma_gemm<<<dim3(48, 2, 1), 256, GSMEM>>>(a);
    }

    // 9: L6: Q,K (split); V (split transposed)
    {
        GArgs a{};
        a.AH[0] = a.AH[1] = a.AH[2] = xH;
        a.AL[0] = a.AL[1] = a.AL[2] = xL;
        a.BH[0] = WqTH; a.BH[1] = WkTH; a.BH[2] = WvTH;
        a.BL[0] = WqTL; a.BL[1] = WkTL; a.BL[2] = WvTL;
        a.CH[0] = QH; a.CL[0] = QL;
        a.CH[1] = KHp; a.CL[1] = KLp;
        a.CH[2] = VTH; a.CL[2] = VTL;
        a.bias[0] = bq; a.bias[1] = bk; a.bias[2] = bv;
        a.M = NND; a.N = NHID; a.K = NHID; a.lda = NHID; a.ldb = NHID; a.ldc = NHID;
        a.estore[0] = 2; a.estore[1] = 2; a.estore[2] = 3;
        mma_gemm<<<dim3(48, 2, 3), 256, GSMEM>>>(a);
    }

    // 10: L7: A_tilde = adj * (Q @ K^T)  (fp32 out)
    {
        GArgs a{};
        a.AH[0] = QH; a.AL[0] = QL;
        a.BH[0] = KHp; a.BL[0] = KLp;
        a.C[0] = attp;
        a.mul = adjp;
        a.M = NND; a.N = NND; a.K = NHID; a.lda = NHID; a.ldb = NHID; a.ldc = NND;
        mma_gemm<<<dim3(48, 48, 1), 256, GSMEM>>>(a);
    }

    // 11
    attn_softmax_k<<<NND, 256>>>();

    // 12: L9: X_tilde = relu(attention @ V)  (fp32 out)
    {
        GArgs a{};
        a.AH[0] = attH; a.AL[0] = attL;
        a.BH[0] = VTH; a.BL[0] = VTL;
        a.C[0] = xtp;
        a.M = NND; a.N = NHID; a.K = NND; a.lda = NND; a.ldb = NND; a.ldc = NHID;
        a.act = 1;
        mma_gemm<<<dim3(48, 2, 1), 256, GSMEM>>>(a);
    }

    // 13, 14
    xtw2_k<<<768, 256>>>(W2);
    final_k<<<768, 256>>>(b2, out);
}

// round 6
// speedup vs baseline: 1.1037x; 1.1037x over previous
#include <cuda_runtime.h>
#include <cuda_bf16.h>
#include <math.h>
#include <stdint.h>

#define NND    6144
#define NFEAT  512
#define NHID   256
#define NCLASS 8
#define ADIM   128

// ---------------- device scratch (no allocations allowed) ----------------
__device__ float g_nzT[3 * NND];
__device__ float g_wfold[3 * NND * 4];
__device__ float g_bfold[3];
__device__ float g_adj[(size_t)NND * NND];
__device__ float g_att[(size_t)NND * NND];
__device__ float g_W1T[NHID * NFEAT];
__device__ float g_WqT[NHID * NHID];
__device__ float g_WkT[NHID * NHID];
__device__ float g_WvT[NHID * NHID];
__device__ float g_fW1T[(size_t)NHID * NND];
__device__ float g_VT[(size_t)NHID * NND];
__device__ float g_Q[(size_t)NND * NHID];
__device__ float g_Kh[(size_t)NND * NHID];
__device__ float g_x[(size_t)NND * NHID];
__device__ float g_xt[(size_t)NND * NHID];
__device__ float g_xtw2[NND * NCLASS];

// ---------------- helpers ----------------
__device__ __forceinline__ uint32_t s2u(const void* p) {
    uint32_t a;
    asm("{ .reg .u64 t; cvta.to.shared.u64 t, %1; cvt.u32.u64 %0, t; }" : "=r"(a) : "l"(p));
    return a;
}
// split (x,y) -> packed bf16x2 hi, packed bf16x2 lo
__device__ __forceinline__ void cvt_split2(float x, float y, uint32_t& hi, uint32_t& lo) {
    __nv_bfloat162 h = __float22bfloat162_rn(make_float2(x, y));
    hi = *reinterpret_cast<uint32_t*>(&h);
    float hx = __uint_as_float(hi << 16);
    float hy = __uint_as_float(hi & 0xFFFF0000u);
    __nv_bfloat162 l = __float22bfloat162_rn(make_float2(x - hx, y - hy));
    lo = *reinterpret_cast<uint32_t*>(&l);
}

#define LDSM4(r, a)                                                                        \
    asm volatile("ldmatrix.sync.aligned.m8n8.x4.shared.b16 {%0,%1,%2,%3}, [%4];"           \
                 : "=r"((r)[0]), "=r"((r)[1]), "=r"((r)[2]), "=r"((r)[3]) : "r"(a))
#define LDSM2(r, a)                                                                        \
    asm volatile("ldmatrix.sync.aligned.m8n8.x2.shared.b16 {%0,%1}, [%2];"                 \
                 : "=r"((r)[0]), "=r"((r)[1]) : "r"(a))

__device__ __forceinline__ void mma16816(float c[4], const uint32_t a[4], const uint32_t b[2]) {
    asm volatile(
        "mma.sync.aligned.m16n8k16.row.col.f32.bf16.bf16.f32 "
        "{%0,%1,%2,%3}, {%4,%5,%6,%7}, {%8,%9}, {%0,%1,%2,%3};"
        : "+f"(c[0]), "+f"(c[1]), "+f"(c[2]), "+f"(c[3])
        : "r"(a[0]), "r"(a[1]), "r"(a[2]), "r"(a[3]), "r"(b[0]), "r"(b[1]));
}

// ---------------- mma.sync GEMM: C = act((A @ B'^T) * mul + bias) ----------------
// A: [M,K] fp32 row-major. B': [N,K] fp32 row-major. Tile 128x128, 8 warps,
// warp tile 64x32, KC=32/iter. bf16 3-term split Ah*Bh + Ah*Bl + Al*Bh, fp32 acc.
// Double-buffered SMEM; fragments (AH/AL/BH/BL) each read once per ks.
struct TCArgs {
    const float* A[3];
    const float* B[3];
    float*       C[3];
    const float* bias[3];
    const float* mul;
    int M, N, K, lda, ldb, ldc, act;
    int tstore[3];         // 1: C stored transposed: C[col*M + m]
};

#define ROWB 80
#define TILEB (128 * ROWB)
#define STAGEB (4 * TILEB)
#define GSMEM (2 * STAGEB)

__global__ void __launch_bounds__(256, 1) mma_gemm(const TCArgs p) {
    extern __shared__ __align__(16) char smem[];

    const int bz = blockIdx.z;
    const float* __restrict__ A    = p.A[bz];
    const float* __restrict__ B    = p.B[bz];
    float* __restrict__       C    = p.C[bz];
    const float* __restrict__ bias = p.bias[bz];

    const int m0 = blockIdx.x * 128, n0 = blockIdx.y * 128;
    const int lda = p.lda, ldb = p.ldb, ldc = p.ldc, K = p.K;

    const int tid  = threadIdx.x;
    const int lane = tid & 31, wid = tid >> 5;
    const int wm = wid & 1, wn = wid >> 1;

    const uint32_t u0 = s2u(smem);
    const uint32_t aRowOff = (uint32_t)((lane & 15) * ROWB + ((lane & 16) ? 16 : 0));
    const uint32_t bRowOff = (uint32_t)((lane & 7) * ROWB + ((lane & 8) ? 16 : 0));

    float acc[4][4][4];
#pragma unroll
    for (int mt = 0; mt < 4; mt++)
#pragma unroll
        for (int nt = 0; nt < 4; nt++)
#pragma unroll
            for (int q = 0; q < 4; q++) acc[mt][nt][q] = 0.f;

    const float* Abase = A + (size_t)m0 * lda;
    const float* Bbase = B + (size_t)n0 * ldb;

    float4 ra[4], rb[4];

    auto loadT = [&](int k0) {
#pragma unroll
        for (int l = 0; l < 4; l++) {
            int idx = tid + l * 256;
            int row = idx >> 3;
            int c4  = (idx & 7) << 2;
            ra[l] = *reinterpret_cast<const float4*>(Abase + (size_t)row * lda + k0 + c4);
            rb[l] = *reinterpret_cast<const float4*>(Bbase + (size_t)row * ldb + k0 + c4);
        }
    };
    auto storeT = [&](int stage) {
        char* AH = smem + stage * STAGEB;
        char* AL = AH + TILEB;
        char* BH = AL + TILEB;
        char* BL = BH + TILEB;
#pragma unroll
        for (int l = 0; l < 4; l++) {
            int idx = tid + l * 256;
            int row = idx >> 3;
            int off = row * ROWB + ((idx & 7) << 3);
            uint32_t h0, l0, h1, l1;
            cvt_split2(ra[l].x, ra[l].y, h0, l0);
            cvt_split2(ra[l].z, ra[l].w, h1, l1);
            *reinterpret_cast<uint2*>(AH + off) = make_uint2(h0, h1);
            *reinterpret_cast<uint2*>(AL + off) = make_uint2(l0, l1);
            cvt_split2(rb[l].x, rb[l].y, h0, l0);
            cvt_split2(rb[l].z, rb[l].w, h1, l1);
            *reinterpret_cast<uint2*>(BH + off) = make_uint2(h0, h1);
            *reinterpret_cast<uint2*>(BL + off) = make_uint2(l0, l1);
        }
    };
    auto compute = [&](int stage) {
        const uint32_t uAH = u0 + (uint32_t)(stage * STAGEB);
        const uint32_t uAL = uAH + TILEB;
        const uint32_t uBH = uAL + TILEB;
        const uint32_t uBL = uBH + TILEB;
#pragma unroll
        for (int ks = 0; ks < 2; ks++) {
            const uint32_t ka = (uint32_t)(ks * 32);
            uint32_t ah[4][4], bh[4][2], bl[4][2];
#pragma unroll
            for (int mt = 0; mt < 4; mt++)
                LDSM4(ah[mt], uAH + (uint32_t)((wm * 64 + mt * 16) * ROWB) + aRowOff + ka);
#pragma unroll
            for (int nt = 0; nt < 4; nt++) {
                uint32_t ro = (uint32_t)((wn * 32 + nt * 8) * ROWB) + bRowOff + ka;
                LDSM2(bh[nt], uBH + ro);
                LDSM2(bl[nt], uBL + ro);
            }
#pragma unroll
            for (int mt = 0; mt < 4; mt++)
#pragma unroll
                for (int nt = 0; nt < 4; nt++) mma16816(acc[mt][nt], ah[mt], bh[nt]);
#pragma unroll
            for (int mt = 0; mt < 4; mt++)
#pragma unroll
                for (int nt = 0; nt < 4; nt++) mma16816(acc[mt][nt], ah[mt], bl[nt]);
            // pass 3: AL * BH (AL fragments loaded once here)
#pragma unroll
            for (int mt = 0; mt < 4; mt++) {
                uint32_t alf[4];
                LDSM4(alf, uAL + (uint32_t)((wm * 64 + mt * 16) * ROWB) + aRowOff + ka);
#pragma unroll
                for (int nt = 0; nt < 4; nt++) mma16816(acc[mt][nt], alf, bh[nt]);
            }
        }
    };

    const int niter = K >> 5;
    loadT(0);
    storeT(0);
    if (niter > 1) loadT(32);
    __syncthreads();
    for (int i = 0; i < niter; i++) {
        if (i + 1 < niter) storeT((i + 1) & 1);
        if (i + 2 < niter) loadT((i + 2) << 5);
        compute(i & 1);
        __syncthreads();
    }

    // ---------------- epilogue ----------------
    const int ts = p.tstore[bz];
    const float* __restrict__ mul = p.mul;
#pragma unroll
    for (int mt = 0; mt < 4; mt++) {
#pragma unroll
        for (int nt = 0; nt < 4; nt++) {
            int mA = m0 + wm * 64 + mt * 16 + (lane >> 2);
            int n  = n0 + wn * 32 + nt * 8 + 2 * (lane & 3);
#pragma unroll
            for (int h = 0; h < 2; h++) {
                int mm = mA + h * 8;
                float vx = acc[mt][nt][2 * h + 0];
                float vy = acc[mt][nt][2 * h + 1];
                if (mul) {
                    float2 mv = *reinterpret_cast<const float2*>(&mul[(size_t)mm * ldc + n]);
                    vx *= mv.x; vy *= mv.y;
                }
                if (bias) { vx += bias[n]; vy += bias[n + 1]; }
                if (p.act) { vx = fmaxf(vx, 0.f); vy = fmaxf(vy, 0.f); }
                if (!ts) {
                    *reinterpret_cast<float2*>(&C[(size_t)mm * ldc + n]) = make_float2(vx, vy);
                } else {
                    C[(size_t)n * p.M + mm]       = vx;
                    C[(size_t)(n + 1) * p.M + mm] = vy;
                }
            }
        }
    }
}

// ---------------- transpose: out[c][r] = in[r][c] ----------------
__global__ void transpose_k(const float* __restrict__ in, float* __restrict__ out,
                            int R, int C) {
    __shared__ float t[32][33];
    int c0 = blockIdx.x * 32, r0 = blockIdx.y * 32;
    int x = threadIdx.x, y = threadIdx.y;
#pragma unroll
    for (int i = 0; i < 32; i += 8) t[y + i][x] = in[(size_t)(r0 + y + i) * C + c0 + x];
    __syncthreads();
#pragma unroll
    for (int i = 0; i < 32; i += 8)
        out[(size_t)(c0 + y + i) * R + r0 + x] = t[x][y + i];
}

// ---- fold: Wfold[l][j][c] = sum_k Wa_l[j,k] * Wagg[l*128+k, c]; bfold = ba@Wagg+bagg
__global__ void fold_k(const float* __restrict__ Wa1, const float* __restrict__ Wa2,
                       const float* __restrict__ Wa3, const float* __restrict__ Wagg,
                       const float* __restrict__ bagg, const float* __restrict__ ba1,
                       const float* __restrict__ ba2, const float* __restrict__ ba3) {
    int j = blockIdx.x * 128 + threadIdx.x;
    int l = blockIdx.y;
    const float* Wa = (l == 0) ? Wa1 : (l == 1) ? Wa2 : Wa3;
    float c0 = 0.f, c1 = 0.f, c2 = 0.f;
    for (int k = 0; k < ADIM; k++) {
        float a = Wa[(size_t)j * ADIM + k];
        const float* wg = &Wagg[(l * ADIM + k) * 3];
        c0 = fmaf(a, wg[0], c0);
        c1 = fmaf(a, wg[1], c1);
        c2 = fmaf(a, wg[2], c2);
    }
    *reinterpret_cast<float4*>(&g_wfold[((size_t)l * NND + j) * 4]) =
        make_float4(c0, c1, c2, 0.f);
    if (blockIdx.x == 0 && l == 0 && threadIdx.x < 3) {
        int c = threadIdx.x;
        float b = bagg[c];
        for (int k = 0; k < ADIM; k++) {
            b += ba1[k] * Wagg[k * 3 + c];
            b += ba2[k] * Wagg[(ADIM + k) * 3 + c];
            b += ba3[k] * Wagg[(2 * ADIM + k) * 3 + c];
        }
        g_bfold[c] = b;
    }
}

// ---- gemv+gate: z4[r,c] = sum_l sum_j adj_l[r,j]*Wfold[l][j][c] + bfold; nz=softmax
#define GV_ROWS 32
#define GV_CH 512
__global__ void gemv_nz_k(const float* __restrict__ a0, const float* __restrict__ a1,
                          const float* __restrict__ a2, float* __restrict__ out_nz,
                          int write_out) {
    __shared__ float sw[9 * GV_CH];
    const int tid = threadIdx.x;
    const int lane = tid & 31, warp = tid >> 5;
    const int rbase = blockIdx.x * GV_ROWS + warp * 4;
    float s[4][3];
#pragma unroll
    for (int r = 0; r < 4; r++)
#pragma unroll
        for (int c = 0; c < 3; c++) s[r][c] = 0.f;

    for (int ch = 0; ch < NND; ch += GV_CH) {
        __syncthreads();
        for (int idx = tid; idx < 3 * GV_CH; idx += 256) {
            int l = idx / GV_CH, j = idx % GV_CH;
            float4 w = *reinterpret_cast<const float4*>(&g_wfold[((size_t)l * NND + ch + j) * 4]);
            sw[(l * 3 + 0) * GV_CH + j] = w.x;
            sw[(l * 3 + 1) * GV_CH + j] = w.y;
            sw[(l * 3 + 2) * GV_CH + j] = w.z;
        }
        __syncthreads();
        for (int j = lane; j < GV_CH; j += 32) {
            float w00 = sw[0 * GV_CH + j], w01 = sw[1 * GV_CH + j], w02 = sw[2 * GV_CH + j];
            float w10 = sw[3 * GV_CH + j], w11 = sw[4 * GV_CH + j], w12 = sw[5 * GV_CH + j];
            float w20 = sw[6 * GV_CH + j], w21 = sw[7 * GV_CH + j], w22 = sw[8 * GV_CH + j];
#pragma unroll
            for (int r = 0; r < 4; r++) {
                size_t off = (size_t)(rbase + r) * NND + ch + j;
                float v0 = a0[off], v1 = a1[off], v2 = a2[off];
                s[r][0] += v0 * w00 + v1 * w10 + v2 * w20;
                s[r][1] += v0 * w01 + v1 * w11 + v2 * w21;
                s[r][2] += v0 * w02 + v1 * w12 + v2 * w22;
            }
        }
    }
#pragma unroll
    for (int r = 0; r < 4; r++)
#pragma unroll
        for (int c = 0; c < 3; c++) {
            float v = s[r][c];
#pragma unroll
            for (int off = 16; off; off >>= 1) v += __shfl_down_sync(0xffffffffu, v, off);
            s[r][c] = v;
        }
    if (lane == 0) {
#pragma unroll
        for (int r = 0; r < 4; r++) {
            int row = rbase + r;
            float z0 = s[r][0] + g_bfold[0];
            float z1 = s[r][1] + g_bfold[1];
            float z2 = s[r][2] + g_bfold[2];
            float mx = fmaxf(z0, fmaxf(z1, z2));
            float e0 = expf(z0 - mx), e1 = expf(z1 - mx), e2 = expf(z2 - mx);
            float inv = 1.f / (e0 + e1 + e2);
            e0 *= inv; e1 *= inv; e2 *= inv;
            g_nzT[0 * NND + row] = e0;
            g_nzT[1 * NND + row] = e1;
            g_nzT[2 * NND + row] = e2;
            if (write_out) {
                out_nz[row * 3 + 0] = e0;
                out_nz[row * 3 + 1] = e1;
                out_nz[row * 3 + 2] = e2;
            }
        }
    }
}

// ---------------- adj[i,j] = nz[j,0]*a0 + nz[j,1]*a1 + nz[j,2]*a2 ----------------
__global__ void build_adj_k(const float* __restrict__ a0, const float* __restrict__ a1,
                            const float* __restrict__ a2) {
    const size_t total4 = (size_t)NND * NND / 4;
    for (size_t e = (size_t)blockIdx.x * blockDim.x + threadIdx.x; e < total4;
         e += (size_t)gridDim.x * blockDim.x) {
        size_t off = e * 4;
        int j = (int)(off % NND);
        float4 w0 = *reinterpret_cast<const float4*>(&g_nzT[j]);
        float4 w1 = *reinterpret_cast<const float4*>(&g_nzT[NND + j]);
        float4 w2 = *reinterpret_cast<const float4*>(&g_nzT[2 * NND + j]);
        float4 x0 = *reinterpret_cast<const float4*>(a0 + off);
        float4 x1 = *reinterpret_cast<const float4*>(a1 + off);
        float4 x2 = *reinterpret_cast<const float4*>(a2 + off);
        float4 r;
        r.x = w0.x * x0.x + w1.x * x1.x + w2.x * x2.x;
        r.y = w0.y * x0.y + w1.y * x1.y + w2.y * x2.y;
        r.z = w0.z * x0.z + w1.z * x1.z + w2.z * x2.z;
        r.w = w0.w * x0.w + w1.w * x1.w + w2.w * x2.w;
        *reinterpret_cast<float4*>(&g_adj[off]) = r;
    }
}

// ---------------- per-row softmax over the 6144-wide attention matrix -----------
__global__ void attn_softmax_k() {
    const int row = blockIdx.x;
    float* __restrict__ ptr = &g_att[(size_t)row * NND];
    const int tid  = threadIdx.x;
    const int lane = tid & 31, warp = tid >> 5;
    float4 v[6];
    float mx = -3.4e38f;
#pragma unroll
    for (int l = 0; l < 6; l++) {
        v[l] = *reinterpret_cast<const float4*>(&ptr[(tid + l * 256) * 4]);
        mx = fmaxf(mx, fmaxf(fmaxf(v[l].x, v[l].y), fmaxf(v[l].z, v[l].w)));
    }
    __shared__ float sm[8], ss[8];
#pragma unroll
    for (int off = 16; off; off >>= 1) mx = fmaxf(mx, __shfl_xor_sync(0xffffffffu, mx, off));
    if (lane == 0) sm[warp] = mx;
    __syncthreads();
    float bm = fmaxf(fmaxf(fmaxf(sm[0], sm[1]), fmaxf(sm[2], sm[3])),
                     fmaxf(fmaxf(sm[4], sm[5]), fmaxf(sm[6], sm[7])));
    float sum = 0.f;
#pragma unroll
    for (int l = 0; l < 6; l++) {
        v[l].x = expf(v[l].x - bm);
        v[l].y = expf(v[l].y - bm);
        v[l].z = expf(v[l].z - bm);
        v[l].w = expf(v[l].w - bm);
        sum += v[l].x + v[l].y + v[l].z + v[l].w;
    }
#pragma unroll
    for (int off = 16; off; off >>= 1) sum += __shfl_xor_sync(0xffffffffu, sum, off);
    if (lane == 0) ss[warp] = sum;
    __syncthreads();
    float tot = ss[0] + ss[1] + ss[2] + ss[3] + ss[4] + ss[5] + ss[6] + ss[7];
    float scale = 1.f / tot;
#pragma unroll
    for (int l = 0; l < 6; l++) {
        v[l].x *= scale; v[l].y *= scale; v[l].z *= scale; v[l].w *= scale;
        *reinterpret_cast<float4*>(&ptr[(tid + l * 256) * 4]) = v[l];
    }
}

// ---------------- X_tilde @ W2 (skinny, N=8) ----------------
__global__ void xtw2_k(const float* __restrict__ W2) {
    int row  = blockIdx.x * 8 + (threadIdx.x >> 5);
    int lane = threadIdx.x & 31;
    if (row >= NND) return;
    const float* xr = &g_xt[(size_t)row * NHID];
    float acc[8] = {0, 0, 0, 0, 0, 0, 0, 0};
    for (int h = lane; h < NHID; h += 32) {
        float xv = xr[h];
        const float4* wp = reinterpret_cast<const float4*>(&W2[h * 8]);
        float4 wlo = wp[0], whi = wp[1];
        acc[0] = fmaf(xv, wlo.x, acc[0]);
        acc[1] = fmaf(xv, wlo.y, acc[1]);
        acc[2] = fmaf(xv, wlo.z, acc[2]);
        acc[3] = fmaf(xv, wlo.w, acc[3]);
        acc[4] = fmaf(xv, whi.x, acc[4]);
        acc[5] = fmaf(xv, whi.y, acc[5]);
        acc[6] = fmaf(xv, whi.z, acc[6]);
        acc[7] = fmaf(xv, whi.w, acc[7]);
    }
#pragma unroll
    for (int c = 0; c < 8; c++)
#pragma unroll
        for (int off = 16; off; off >>= 1) acc[c] += __shfl_down_sync(0xffffffffu, acc[c], off);
    if (lane == 0) {
#pragma unroll
        for (int c = 0; c < 8; c++) g_xtw2[row * 8 + c] = acc[c];
    }
}

// ---------------- z = adj @ xtw2 + b2 ; out = softmax(z, axis=1). 8 rows/CTA ----
__global__ void final_k(const float* __restrict__ b2, float* __restrict__ out) {
    const int r0  = blockIdx.x * 8;
    const int tid = threadIdx.x;
    float acc[8][8];
#pragma unroll
    for (int r = 0; r < 8; r++)
#pragma unroll
        for (int c = 0; c < 8; c++) acc[r][c] = 0.f;

    for (int j4 = tid; j4 < NND / 4; j4 += 256) {
        float4 w[8];
        const float4* wp = reinterpret_cast<const float4*>(&g_xtw2[(size_t)j4 * 32]);
#pragma unroll
        for (int q = 0; q < 8; q++) w[q] = wp[q];
#pragma unroll
        for (int r = 0; r < 8; r++) {
            float4 a = *reinterpret_cast<const float4*>(&g_adj[(size_t)(r0 + r) * NND + j4 * 4]);
            float av[4] = {a.x, a.y, a.z, a.w};
#pragma unroll
            for (int q = 0; q < 4; q++) {
                acc[r][0] = fmaf(av[q], w[2 * q].x, acc[r][0]);
                acc[r][1] = fmaf(av[q], w[2 * q].y, acc[r][1]);
                acc[r][2] = fmaf(av[q], w[2 * q].z, acc[r][2]);
                acc[r][3] = fmaf(av[q], w[2 * q].w, acc[r][3]);
                acc[r][4] = fmaf(av[q], w[2 * q + 1].x, acc[r][4]);
                acc[r][5] = fmaf(av[q], w[2 * q + 1].y, acc[r][5]);
                acc[r][6] = fmaf(av[q], w[2 * q + 1].z, acc[r][6]);
                acc[r][7] = fmaf(av[q], w[2 * q + 1].w, acc[r][7]);
            }
        }
    }

    __shared__ float sred[8][64];
    const int lane = tid & 31, warp = tid >> 5;
#pragma unroll
    for (int r = 0; r < 8; r++)
#pragma unroll
        for (int c = 0; c < 8; c++) {
            float vv = acc[r][c];
#pragma unroll
            for (int off = 16; off; off >>= 1) vv += __shfl_down_sync(0xffffffffu, vv, off);
            if (lane == 0) sred[warp][r * 8 + c] = vv;
        }
    __syncthreads();
    if (tid < 64) {
        float v = 0.f;
#pragma unroll
        for (int w = 0; w < 8; w++) v += sred[w][tid];
        int c = tid & 7;
        v += b2[c];
        float mx = v;
#pragma unroll
        for (int off = 4; off; off >>= 1) mx = fmaxf(mx, __shfl_xor_sync(0xffffffffu, mx, off, 8));
        float e = expf(v - mx);
        float s = e;
#pragma unroll
        for (int off = 4; off; off >>= 1) s += __shfl_xor_sync(0xffffffffu, s, off, 8);
        out[(size_t)(r0 + (tid >> 3)) * 8 + c] = e / s;
    }
}

// ---------------- host side ----------------
static float* symaddr(const void* sym) {
    void* p = nullptr;
    cudaGetSymbolAddress(&p, sym);
    return (float*)p;
}

extern "C" void kernel_launch(void* const* d_in, const int* in_sizes, int n_in,
                              void* d_out, int out_size) {
    const float* adj0 = (const float*)d_in[0];
    const float* adj1 = (const float*)d_in[1];
    const float* adj2 = (const float*)d_in[2];
    const float* feats = (const float*)d_in[3];
    const float* Wa1 = (const float*)d_in[4];
    const float* ba1 = (const float*)d_in[5];
    const float* Wa2 = (const float*)d_in[6];
    const float* ba2 = (const float*)d_in[7];
    const float* Wa3 = (const float*)d_in[8];
    const float* ba3 = (const float*)d_in[9];
    const float* Wagg = (const float*)d_in[10];
    const float* bagg = (const float*)d_in[11];
    const float* W1 = (const float*)d_in[12];
    const float* b1 = (const float*)d_in[13];
    const float* Wq = (const float*)d_in[14];
    const float* bq = (const float*)d_in[15];
    const float* Wk = (const float*)d_in[16];
    const float* bk = (const float*)d_in[17];
    const float* Wv = (const float*)d_in[18];
    const float* bv = (const float*)d_in[19];
    const float* W2 = (const float*)d_in[20];
    const float* b2 = (const float*)d_in[21];
    float* out = (float*)d_out;

    float* adjp  = symaddr(g_adj);
    float* attp  = symaddr(g_att);
    float* W1Tp  = symaddr(g_W1T);
    float* WqTp  = symaddr(g_WqT);
    float* WkTp  = symaddr(g_WkT);
    float* WvTp  = symaddr(g_WvT);
    float* fW1Tp = symaddr(g_fW1T);
    float* VTp   = symaddr(g_VT);
    float* Qp    = symaddr(g_Q);
    float* Kp    = symaddr(g_Kh);
    float* xp    = symaddr(g_x);
    float* xtp   = symaddr(g_xt);

    cudaFuncSetAttribute(mma_gemm, cudaFuncAttributeMaxDynamicSharedMemorySize, GSMEM);

    int write_nz = (out_size >= NND * (NCLASS + 3)) ? 1 : 0;

    // 0: W1 transpose
    transpose_k<<<dim3(NHID / 32, NFEAT / 32), dim3(32, 8)>>>(W1, W1Tp, NFEAT, NHID);
    // 1: fold Wa_i @ Wagg_i -> Wfold (and bfold)
    fold_k<<<dim3(NND / 128, 3), 128>>>(Wa1, Wa2, Wa3, Wagg, bagg, ba1, ba2, ba3);
    // 2: gemv + gate softmax -> nz
    gemv_nz_k<<<NND / GV_ROWS, 256>>>(adj0, adj1, adj2, out + (size_t)NND * NCLASS, write_nz);

    // 3: L4: fW1^T = (feats @ W1)^T   <-- profiled launch (index 3)
    {
        TCArgs a{};
        a.A[0] = feats;
        a.B[0] = W1Tp;
        a.C[0] = fW1Tp;
        a.M = NND; a.N = NHID; a.K = NFEAT; a.lda = NFEAT; a.ldb = NFEAT; a.ldc = NHID;
        a.tstore[0] = 1;
        mma_gemm<<<dim3(48, 2, 1), 256, GSMEM>>>(a);
    }

    // 4-6: Wq/Wk/Wv transposes
    transpose_k<<<dim3(NHID / 32, NHID / 32), dim3(32, 8)>>>(Wq, WqTp, NHID, NHID);
    transpose_k<<<dim3(NHID / 32, NHID / 32), dim3(32, 8)>>>(Wk, WkTp, NHID, NHID);
    transpose_k<<<dim3(NHID / 32, NHID / 32), dim3(32, 8)>>>(Wv, WvTp, NHID, NHID);

    // 7: fused adjacency
    build_adj_k<<<1184, 256>>>(adj0, adj1, adj2);

    // 8: L5: x = relu(adj @ fW1 + b1)
    {
        TCArgs a{};
        a.A[0] = adjp;
        a.B[0] = fW1Tp;
        a.C[0] = xp;
        a.bias[0] = b1;
        a.M = NND; a.N = NHID; a.K = NND; a.lda = NND; a.ldb = NND; a.ldc = NHID; a.act = 1;
        mma_gemm<<<dim3(48, 2, 1), 256, GSMEM>>>(a);
    }

    // 9: L6: Q/K normal; V stored transposed (batched)
    {
        TCArgs a{};
        a.A[0] = a.A[1] = a.A[2] = xp;
        a.B[0] = WqTp; a.B[1] = WkTp; a.B[2] = WvTp;
        a.C[0] = Qp; a.C[1] = Kp; a.C[2] = VTp;
        a.bias[0] = bq; a.bias[1] = bk; a.bias[2] = bv;
        a.M = NND; a.N = NHID; a.K = NHID; a.lda = NHID; a.ldb = NHID; a.ldc = NHID;
        a.tstore[0] = 0; a.tstore[1] = 0; a.tstore[2] = 1;
        mma_gemm<<<dim3(48, 2, 3), 256, GSMEM>>>(a);
    }

    // 10: L7: A_tilde = adj * (Q @ K^T)
    {
        TCArgs a{};
        a.A[0] = Qp;
        a.B[0] = Kp;
        a.C[0] = attp;
        a.mul = adjp;
        a.M = NND; a.N = NND; a.K = NHID; a.lda = NHID; a.ldb = NHID; a.ldc = NND;
        mma_gemm<<<dim3(48, 48, 1), 256, GSMEM>>>(a);
    }

    // 11: row softmax
    attn_softmax_k<<<NND, 256>>>();

    // 12: L9: X_tilde = relu(attention @ V)
    {
        TCArgs a{};
        a.A[0] = attp;
        a.B[0] = VTp;
        a.C[0] = xtp;
        a.M = NND; a.N = NHID; a.K = NND; a.lda = NND; a.ldb = NND; a.ldc = NHID; a.act = 1;
        mma_gemm<<<dim3(48, 2, 1), 256, GSMEM>>>(a);
    }

    // 13, 14
    xtw2_k<<<768, 256>>>(W2);
    final_k<<<768, 256>>>(b2, out);
}

// round 7
// speedup vs baseline: 1.1876x; 1.0760x over previous
#include <cuda_runtime.h>
#include <cuda_bf16.h>
#include <math.h>
#include <stdint.h>

#define NND    6144
#define NFEAT  512
#define NHID   256
#define NCLASS 8
#define ADIM   128

typedef __nv_bfloat16 bf16;

// ---------------- device scratch (no allocations allowed) ----------------
__device__ float g_nzT[3 * NND];
__device__ float g_wfold[3 * NND * 4];
__device__ float g_bfold[3];
__device__ float g_adj[(size_t)NND * NND];         // fp32 (L7 mul + final)
__device__ float g_att[(size_t)NND * NND];         // fp32 logits (softmax in)
__device__ float g_part[3 * (size_t)NND * NHID];   // split-K partials
__device__ float g_xt[(size_t)NND * NHID];
__device__ float g_xtw2[NND * NCLASS];

__device__ bf16 g_adjH[(size_t)NND * NND],   g_adjL[(size_t)NND * NND];
__device__ bf16 g_attH[(size_t)NND * NND],   g_attL[(size_t)NND * NND];
__device__ bf16 g_featsH[(size_t)NND * NFEAT], g_featsL[(size_t)NND * NFEAT];
__device__ bf16 g_W1TH[NHID * NFEAT],  g_W1TL[NHID * NFEAT];
__device__ bf16 g_WqTH[NHID * NHID],   g_WqTL[NHID * NHID];
__device__ bf16 g_WkTH[NHID * NHID],   g_WkTL[NHID * NHID];
__device__ bf16 g_WvTH[NHID * NHID],   g_WvTL[NHID * NHID];
__device__ bf16 g_fW1TH[(size_t)NHID * NND], g_fW1TL[(size_t)NHID * NND];
__device__ bf16 g_xH[(size_t)NND * NHID],  g_xL[(size_t)NND * NHID];
__device__ bf16 g_QH[(size_t)NND * NHID],  g_QL[(size_t)NND * NHID];
__device__ bf16 g_KHb[(size_t)NND * NHID], g_KLb[(size_t)NND * NHID];
__device__ bf16 g_VTH[(size_t)NHID * NND], g_VTL[(size_t)NHID * NND];

// ---------------- helpers ----------------
__device__ __forceinline__ uint32_t s2u(const void* p) {
    uint32_t a;
    asm("{ .reg .u64 t; cvta.to.shared.u64 t, %1; cvt.u32.u64 %0, t; }" : "=r"(a) : "l"(p));
    return a;
}
__device__ __forceinline__ void split1(float v, bf16& h, bf16& l) {
    h = __float2bfloat16(v);
    l = __float2bfloat16(v - __bfloat162float(h));
}
__device__ __forceinline__ void cvt_split2(float x, float y, uint32_t& hi, uint32_t& lo) {
    __nv_bfloat162 h = __float22bfloat162_rn(make_float2(x, y));
    hi = *reinterpret_cast<uint32_t*>(&h);
    float hx = __uint_as_float(hi << 16);
    float hy = __uint_as_float(hi & 0xFFFF0000u);
    __nv_bfloat162 l = __float22bfloat162_rn(make_float2(x - hx, y - hy));
    lo = *reinterpret_cast<uint32_t*>(&l);
}
__device__ __forceinline__ void split4(float4 v, uint2& h, uint2& l) {
    cvt_split2(v.x, v.y, h.x, l.x);
    cvt_split2(v.z, v.w, h.y, l.y);
}

#define LDSM4(r, a)                                                                        \
    asm volatile("ldmatrix.sync.aligned.m8n8.x4.shared.b16 {%0,%1,%2,%3}, [%4];"           \
                 : "=r"((r)[0]), "=r"((r)[1]), "=r"((r)[2]), "=r"((r)[3]) : "r"(a))
#define LDSM2(r, a)                                                                        \
    asm volatile("ldmatrix.sync.aligned.m8n8.x2.shared.b16 {%0,%1}, [%2];"                 \
                 : "=r"((r)[0]), "=r"((r)[1]) : "r"(a))

__device__ __forceinline__ void mma16816(float c[4], const uint32_t a[4], const uint32_t b[2]) {
    asm volatile(
        "mma.sync.aligned.m16n8k16.row.col.f32.bf16.bf16.f32 "
        "{%0,%1,%2,%3}, {%4,%5,%6,%7}, {%8,%9}, {%0,%1,%2,%3};"
        : "+f"(c[0]), "+f"(c[1]), "+f"(c[2]), "+f"(c[3])
        : "r"(a[0]), "r"(a[1]), "r"(a[2]), "r"(a[3]), "r"(b[0]), "r"(b[1]));
}

// ---------------- GEMM: C = act((A @ B'^T) * mul + bias) ----------------
// A,B pre-split bf16 H/L. A: [M,K] (lda). B': [N,K] (ldb). Tile 128x128, 8 warps,
// warp tile 64x32, KC=32/iter. 3-term split Ah*Bh + Ah*Bl + Al*Bh, fp32 acc.
// kLen != 0 => blockIdx.z is a K-chunk (split-K, C[z] = partial fp32).
struct GArgs {
    const bf16* AH[3]; const bf16* AL[3];
    const bf16* BH[3]; const bf16* BL[3];
    float* C[3];
    bf16* CH[3]; bf16* CL[3];
    const float* bias[3];
    const float* mul;
    int M, N, K, lda, ldb, ldc, act;
    int kLen;            // 0: bz = batch index; else bz = K-chunk index
    int estore[3];       // 0 fp32, 2 split, 3 split transposed
};

#define ROWB 80
#define TILEB (128 * ROWB)
#define STAGEB (4 * TILEB)
#define GSMEM (2 * STAGEB)

__global__ void __launch_bounds__(256, 1) mma_gemm(const GArgs p) {
    extern __shared__ __align__(16) char smem[];

    const int bz = blockIdx.z;
    const int bi = p.kLen ? 0 : bz;
    const int kOff = p.kLen ? bz * p.kLen : 0;
    const int Kloc = p.kLen ? p.kLen : p.K;

    const int m0 = blockIdx.x * 128, n0 = blockIdx.y * 128;
    const int lda = p.lda, ldb = p.ldb, ldc = p.ldc;

    const bf16* __restrict__ pAH = p.AH[bi] + (size_t)m0 * lda + kOff;
    const bf16* __restrict__ pAL = p.AL[bi] + (size_t)m0 * lda + kOff;
    const bf16* __restrict__ pBH = p.BH[bi] + (size_t)n0 * ldb + kOff;
    const bf16* __restrict__ pBL = p.BL[bi] + (size_t)n0 * ldb + kOff;
    const float* __restrict__ bias = p.bias[bi];

    const int tid  = threadIdx.x;
    const int lane = tid & 31, wid = tid >> 5;
    const int wm = wid & 1, wn = wid >> 1;

    const uint32_t u0 = s2u(smem);
    const uint32_t aRowOff = (uint32_t)((lane & 15) * ROWB + ((lane & 16) ? 16 : 0));
    const uint32_t bRowOff = (uint32_t)((lane & 7) * ROWB + ((lane & 8) ? 16 : 0));

    float acc[4][4][4];
#pragma unroll
    for (int mt = 0; mt < 4; mt++)
#pragma unroll
        for (int nt = 0; nt < 4; nt++)
#pragma unroll
            for (int q = 0; q < 4; q++) acc[mt][nt][q] = 0.f;

    uint4 rah[2], ral[2], rbh[2], rbl[2];

    // per-thread fill: idx = tid + l*256; row = idx>>2; 8 bf16 (16B) per chunk
    auto loadT = [&](int k0) {
#pragma unroll
        for (int l = 0; l < 2; l++) {
            int idx = tid + l * 256;
            int row = idx >> 2;
            int c8  = (idx & 3) << 3;
            rah[l] = *reinterpret_cast<const uint4*>(pAH + (size_t)row * lda + k0 + c8);
            ral[l] = *reinterpret_cast<const uint4*>(pAL + (size_t)row * lda + k0 + c8);
            rbh[l] = *reinterpret_cast<const uint4*>(pBH + (size_t)row * ldb + k0 + c8);
            rbl[l] = *reinterpret_cast<const uint4*>(pBL + (size_t)row * ldb + k0 + c8);
        }
    };
    auto storeT = [&](int stage) {
        char* AHs = smem + stage * STAGEB;
        char* ALs = AHs + TILEB;
        char* BHs = ALs + TILEB;
        char* BLs = BHs + TILEB;
#pragma unroll
        for (int l = 0; l < 2; l++) {
            int idx = tid + l * 256;
            int row = idx >> 2;
            int off = row * ROWB + ((idx & 3) << 4);
            *reinterpret_cast<uint4*>(AHs + off) = rah[l];
            *reinterpret_cast<uint4*>(ALs + off) = ral[l];
            *reinterpret_cast<uint4*>(BHs + off) = rbh[l];
            *reinterpret_cast<uint4*>(BLs + off) = rbl[l];
        }
    };
    auto compute = [&](int stage) {
        const uint32_t uAH = u0 + (uint32_t)(stage * STAGEB);
        const uint32_t uAL = uAH + TILEB;
        const uint32_t uBH = uAL + TILEB;
        const uint32_t uBL = uBH + TILEB;
#pragma unroll
        for (int ks = 0; ks < 2; ks++) {
            const uint32_t ka = (uint32_t)(ks * 32);
            uint32_t ah[4][4], bh[4][2], bl[4][2];
#pragma unroll
            for (int mt = 0; mt < 4; mt++)
                LDSM4(ah[mt], uAH + (uint32_t)((wm * 64 + mt * 16) * ROWB) + aRowOff + ka);
#pragma unroll
            for (int nt = 0; nt < 4; nt++) {
                uint32_t ro = (uint32_t)((wn * 32 + nt * 8) * ROWB) + bRowOff + ka;
                LDSM2(bh[nt], uBH + ro);
                LDSM2(bl[nt], uBL + ro);
            }
#pragma unroll
            for (int mt = 0; mt < 4; mt++)
#pragma unroll
                for (int nt = 0; nt < 4; nt++) mma16816(acc[mt][nt], ah[mt], bh[nt]);
#pragma unroll
            for (int mt = 0; mt < 4; mt++)
#pragma unroll
                for (int nt = 0; nt < 4; nt++) mma16816(acc[mt][nt], ah[mt], bl[nt]);
#pragma unroll
            for (int mt = 0; mt < 4; mt++) {
                uint32_t alf[4];
                LDSM4(alf, uAL + (uint32_t)((wm * 64 + mt * 16) * ROWB) + aRowOff + ka);
#pragma unroll
                for (int nt = 0; nt < 4; nt++) mma16816(acc[mt][nt], alf, bh[nt]);
            }
        }
    };

    const int niter = Kloc >> 5;
    loadT(0);
    storeT(0);
    if (niter > 1) loadT(32);
    __syncthreads();
    for (int i = 0; i < niter; i++) {
        if (i + 1 < niter) storeT((i + 1) & 1);
        if (i + 2 < niter) loadT((i + 2) << 5);
        compute(i & 1);
        __syncthreads();
    }

    // ---------------- epilogue ----------------
    const int es = p.estore[bz];
    float* __restrict__ C  = p.C[bz];
    bf16* __restrict__ CH = p.CH[bz];
    bf16* __restrict__ CL = p.CL[bz];
    const float* __restrict__ mul = p.mul;
#pragma unroll
    for (int mt = 0; mt < 4; mt++) {
#pragma unroll
        for (int nt = 0; nt < 4; nt++) {
            int mA = m0 + wm * 64 + mt * 16 + (lane >> 2);
            int n  = n0 + wn * 32 + nt * 8 + 2 * (lane & 3);
#pragma unroll
            for (int h = 0; h < 2; h++) {
                int mm = mA + h * 8;
                float vx = acc[mt][nt][2 * h + 0];
                float vy = acc[mt][nt][2 * h + 1];
                if (mul) {
                    float2 mv = *reinterpret_cast<const float2*>(&mul[(size_t)mm * ldc + n]);
                    vx *= mv.x; vy *= mv.y;
                }
                if (bias) { vx += bias[n]; vy += bias[n + 1]; }
                if (p.act) { vx = fmaxf(vx, 0.f); vy = fmaxf(vy, 0.f); }
                if (es == 0) {
                    *reinterpret_cast<float2*>(&C[(size_t)mm * ldc + n]) = make_float2(vx, vy);
                } else if (es == 2) {
                    uint32_t hi, lo;
                    cvt_split2(vx, vy, hi, lo);
                    *reinterpret_cast<uint32_t*>(&CH[(size_t)mm * ldc + n]) = hi;
                    *reinterpret_cast<uint32_t*>(&CL[(size_t)mm * ldc + n]) = lo;
                } else {  // 3: split transposed
                    bf16 hx, lx, hy, ly;
                    split1(vx, hx, lx);
                    split1(vy, hy, ly);
                    CH[(size_t)n * p.M + mm] = hx;
                    CL[(size_t)n * p.M + mm] = lx;
                    CH[(size_t)(n + 1) * p.M + mm] = hy;
                    CL[(size_t)(n + 1) * p.M + mm] = ly;
                }
            }
        }
    }
}

// ---- split-K reduce: x = relu(sum part + bias) -> bf16 H/L ----
__global__ void reduce_split_k(const float* __restrict__ bias, bf16* __restrict__ oH,
                               bf16* __restrict__ oL) {
    const int n4 = NND * NHID / 4;
    const size_t S = (size_t)NND * NHID;
    for (int e = blockIdx.x * blockDim.x + threadIdx.x; e < n4; e += gridDim.x * blockDim.x) {
        float4 a = reinterpret_cast<const float4*>(g_part)[e];
        float4 b = reinterpret_cast<const float4*>(g_part + S)[e];
        float4 c = reinterpret_cast<const float4*>(g_part + 2 * S)[e];
        int col = (e * 4) & (NHID - 1);
        float4 v;
        v.x = fmaxf(a.x + b.x + c.x + bias[col + 0], 0.f);
        v.y = fmaxf(a.y + b.y + c.y + bias[col + 1], 0.f);
        v.z = fmaxf(a.z + b.z + c.z + bias[col + 2], 0.f);
        v.w = fmaxf(a.w + b.w + c.w + bias[col + 3], 0.f);
        uint2 h, l;
        split4(v, h, l);
        reinterpret_cast<uint2*>(oH)[e] = h;
        reinterpret_cast<uint2*>(oL)[e] = l;
    }
}
// ---- split-K reduce: xt = relu(sum part) -> fp32 ----
__global__ void reduce_f32_k(float* __restrict__ o) {
    const int n4 = NND * NHID / 4;
    const size_t S = (size_t)NND * NHID;
    for (int e = blockIdx.x * blockDim.x + threadIdx.x; e < n4; e += gridDim.x * blockDim.x) {
        float4 a = reinterpret_cast<const float4*>(g_part)[e];
        float4 b = reinterpret_cast<const float4*>(g_part + S)[e];
        float4 c = reinterpret_cast<const float4*>(g_part + 2 * S)[e];
        float4 v;
        v.x = fmaxf(a.x + b.x + c.x, 0.f);
        v.y = fmaxf(a.y + b.y + c.y, 0.f);
        v.z = fmaxf(a.z + b.z + c.z, 0.f);
        v.w = fmaxf(a.w + b.w + c.w, 0.f);
        reinterpret_cast<float4*>(o)[e] = v;
    }
}

// ---------------- transpose + split ----------------
struct TSArgs {
    const float* in[3];
    bf16* oH[3]; bf16* oL[3];
    int R, C;
};
__global__ void transpose_split_k(const TSArgs p) {
    __shared__ float t[32][33];
    const float* __restrict__ in = p.in[blockIdx.z];
    bf16* __restrict__ oH = p.oH[blockIdx.z];
    bf16* __restrict__ oL = p.oL[blockIdx.z];
    const int R = p.R, C = p.C;
    int c0 = blockIdx.x * 32, r0 = blockIdx.y * 32;
    int x = threadIdx.x, y = threadIdx.y;
#pragma unroll
    for (int i = 0; i < 32; i += 8) t[y + i][x] = in[(size_t)(r0 + y + i) * C + c0 + x];
    __syncthreads();
#pragma unroll
    for (int i = 0; i < 32; i += 8) {
        float v = t[x][y + i];
        bf16 h, l;
        split1(v, h, l);
        oH[(size_t)(c0 + y + i) * R + r0 + x] = h;
        oL[(size_t)(c0 + y + i) * R + r0 + x] = l;
    }
}

// ---------------- elementwise split ----------------
__global__ void split_k(const float* __restrict__ in, bf16* __restrict__ oH,
                        bf16* __restrict__ oL, int n4) {
    for (int e = blockIdx.x * blockDim.x + threadIdx.x; e < n4; e += gridDim.x * blockDim.x) {
        float4 v = reinterpret_cast<const float4*>(in)[e];
        uint2 h, l;
        split4(v, h, l);
        reinterpret_cast<uint2*>(oH)[e] = h;
        reinterpret_cast<uint2*>(oL)[e] = l;
    }
}

// ---- fold: Wfold[l][j][c] = sum_k Wa_l[j,k] * Wagg[l*128+k, c]; bfold = ba@Wagg+bagg
__global__ void fold_k(const float* __restrict__ Wa1, const float* __restrict__ Wa2,
                       const float* __restrict__ Wa3, const float* __restrict__ Wagg,
                       const float* __restrict__ bagg, const float* __restrict__ ba1,
                       const float* __restrict__ ba2, const float* __restrict__ ba3) {
    int j = blockIdx.x * 128 + threadIdx.x;
    int l = blockIdx.y;
    const float* Wa = (l == 0) ? Wa1 : (l == 1) ? Wa2 : Wa3;
    float c0 = 0.f, c1 = 0.f, c2 = 0.f;
    for (int k = 0; k < ADIM; k++) {
        float a = Wa[(size_t)j * ADIM + k];
        const float* wg = &Wagg[(l * ADIM + k) * 3];
        c0 = fmaf(a, wg[0], c0);
        c1 = fmaf(a, wg[1], c1);
        c2 = fmaf(a, wg[2], c2);
    }
    *reinterpret_cast<float4*>(&g_wfold[((size_t)l * NND + j) * 4]) =
        make_float4(c0, c1, c2, 0.f);
    if (blockIdx.x == 0 && l == 0 && threadIdx.x < 3) {
        int c = threadIdx.x;
        float b = bagg[c];
        for (int k = 0; k < ADIM; k++) {
            b += ba1[k] * Wagg[k * 3 + c];
            b += ba2[k] * Wagg[(ADIM + k) * 3 + c];
            b += ba3[k] * Wagg[(2 * ADIM + k) * 3 + c];
        }
        g_bfold[c] = b;
    }
}

// ---- gemv+gate: z4[r,c] = sum_l sum_j adj_l[r,j]*Wfold[l][j][c] + bfold; nz=softmax
#define GV_ROWS 32
#define GV_CH 512
__global__ void gemv_nz_k(const float* __restrict__ a0, const float* __restrict__ a1,
                          const float* __restrict__ a2, float* __restrict__ out_nz,
                          int write_out) {
    __shared__ float sw[9 * GV_CH];
    const int tid = threadIdx.x;
    const int lane = tid & 31, warp = tid >> 5;
    const int rbase = blockIdx.x * GV_ROWS + warp * 4;
    float s[4][3];
#pragma unroll
    for (int r = 0; r < 4; r++)
#pragma unroll
        for (int c = 0; c < 3; c++) s[r][c] = 0.f;

    for (int ch = 0; ch < NND; ch += GV_CH) {
        __syncthreads();
        for (int idx = tid; idx < 3 * GV_CH; idx += 256) {
            int l = idx / GV_CH, j = idx % GV_CH;
            float4 w = *reinterpret_cast<const float4*>(&g_wfold[((size_t)l * NND + ch + j) * 4]);
            sw[(l * 3 + 0) * GV_CH + j] = w.x;
            sw[(l * 3 + 1) * GV_CH + j] = w.y;
            sw[(l * 3 + 2) * GV_CH + j] = w.z;
        }
        __syncthreads();
        for (int j = lane; j < GV_CH; j += 32) {
            float w00 = sw[0 * GV_CH + j], w01 = sw[1 * GV_CH + j], w02 = sw[2 * GV_CH + j];
            float w10 = sw[3 * GV_CH + j], w11 = sw[4 * GV_CH + j], w12 = sw[5 * GV_CH + j];
            float w20 = sw[6 * GV_CH + j], w21 = sw[7 * GV_CH + j], w22 = sw[8 * GV_CH + j];
#pragma unroll
            for (int r = 0; r < 4; r++) {
                size_t off = (size_t)(rbase + r) * NND + ch + j;
                float v0 = a0[off], v1 = a1[off], v2 = a2[off];
                s[r][0] += v0 * w00 + v1 * w10 + v2 * w20;
                s[r][1] += v0 * w01 + v1 * w11 + v2 * w21;
                s[r][2] += v0 * w02 + v1 * w12 + v2 * w22;
            }
        }
    }
#pragma unroll
    for (int r = 0; r < 4; r++)
#pragma unroll
        for (int c = 0; c < 3; c++) {
            float v = s[r][c];
#pragma unroll
            for (int off = 16; off; off >>= 1) v += __shfl_down_sync(0xffffffffu, v, off);
            s[r][c] = v;
        }
    if (lane == 0) {
#pragma unroll
        for (int r = 0; r < 4; r++) {
            int row = rbase + r;
            float z0 = s[r][0] + g_bfold[0];
            float z1 = s[r][1] + g_bfold[1];
            float z2 = s[r][2] + g_bfold[2];
            float mx = fmaxf(z0, fmaxf(z1, z2));
            float e0 = expf(z0 - mx), e1 = expf(z1 - mx), e2 = expf(z2 - mx);
            float inv = 1.f / (e0 + e1 + e2);
            e0 *= inv; e1 *= inv; e2 *= inv;
            g_nzT[0 * NND + row] = e0;
            g_nzT[1 * NND + row] = e1;
            g_nzT[2 * NND + row] = e2;
            if (write_out) {
                out_nz[row * 3 + 0] = e0;
                out_nz[row * 3 + 1] = e1;
                out_nz[row * 3 + 2] = e2;
            }
        }
    }
}

// ---- adj = col-weighted mix; emit fp32 + bf16 split ----
__global__ void build_adj_k(const float* __restrict__ a0, const float* __restrict__ a1,
                            const float* __restrict__ a2) {
    const size_t total4 = (size_t)NND * NND / 4;
    for (size_t e = (size_t)blockIdx.x * blockDim.x + threadIdx.x; e < total4;
         e += (size_t)gridDim.x * blockDim.x) {
        size_t off = e * 4;
        int j = (int)(off % NND);
        float4 w0 = *reinterpret_cast<const float4*>(&g_nzT[j]);
        float4 w1 = *reinterpret_cast<const float4*>(&g_nzT[NND + j]);
        float4 w2 = *reinterpret_cast<const float4*>(&g_nzT[2 * NND + j]);
        float4 x0 = *reinterpret_cast<const float4*>(a0 + off);
        float4 x1 = *reinterpret_cast<const float4*>(a1 + off);
        float4 x2 = *reinterpret_cast<const float4*>(a2 + off);
        float4 r;
        r.x = w0.x * x0.x + w1.x * x1.x + w2.x * x2.x;
        r.y = w0.y * x0.y + w1.y * x1.y + w2.y * x2.y;
        r.z = w0.z * x0.z + w1.z * x1.z + w2.z * x2.z;
        r.w = w0.w * x0.w + w1.w * x1.w + w2.w * x2.w;
        *reinterpret_cast<float4*>(&g_adj[off]) = r;
        uint2 h, l;
        split4(r, h, l);
        *reinterpret_cast<uint2*>(&g_adjH[off]) = h;
        *reinterpret_cast<uint2*>(&g_adjL[off]) = l;
    }
}

// ---- per-row softmax over 6144-wide fp32 logits; emit bf16 split ----
__global__ void attn_softmax_k() {
    const int row = blockIdx.x;
    const float* __restrict__ ptr = &g_att[(size_t)row * NND];
    const int tid  = threadIdx.x;
    const int lane = tid & 31, warp = tid >> 5;
    float4 v[6];
    float mx = -3.4e38f;
#pragma unroll
    for (int l = 0; l < 6; l++) {
        v[l] = *reinterpret_cast<const float4*>(&ptr[(tid + l * 256) * 4]);
        mx = fmaxf(mx, fmaxf(fmaxf(v[l].x, v[l].y), fmaxf(v[l].z, v[l].w)));
    }
    __shared__ float sm[8], ss[8];
#pragma unroll
    for (int off = 16; off; off >>= 1) mx = fmaxf(mx, __shfl_xor_sync(0xffffffffu, mx, off));
    if (lane == 0) sm[warp] = mx;
    __syncthreads();
    float bm = fmaxf(fmaxf(fmaxf(sm[0], sm[1]), fmaxf(sm[2], sm[3])),
                     fmaxf(fmaxf(sm[4], sm[5]), fmaxf(sm[6], sm[7])));
    float sum = 0.f;
#pragma unroll
    for (int l = 0; l < 6; l++) {
        v[l].x = expf(v[l].x - bm);
        v[l].y = expf(v[l].y - bm);
        v[l].z = expf(v[l].z - bm);
        v[l].w = expf(v[l].w - bm);
        sum += v[l].x + v[l].y + v[l].z + v[l].w;
    }
#pragma unroll
    for (int off = 16; off; off >>= 1) sum += __shfl_xor_sync(0xffffffffu, sum, off);
    if (lane == 0) ss[warp] = sum;
    __syncthreads();
    float tot = ss[0] + ss[1] + ss[2] + ss[3] + ss[4] + ss[5] + ss[6] + ss[7];
    float scale = 1.f / tot;
#pragma unroll
    for (int l = 0; l < 6; l++) {
        v[l].x *= scale; v[l].y *= scale; v[l].z *= scale; v[l].w *= scale;
        uint2 h, lo;
        split4(v[l], h, lo);
        size_t off = (size_t)row * NND + (tid + l * 256) * 4;
        *reinterpret_cast<uint2*>(&g_attH[off]) = h;
        *reinterpret_cast<uint2*>(&g_attL[off]) = lo;
    }
}

// ---------------- X_tilde @ W2 (skinny, N=8) ----------------
__global__ void xtw2_k(const float* __restrict__ W2) {
    int row  = blockIdx.x * 8 + (threadIdx.x >> 5);
    int lane = threadIdx.x & 31;
    if (row >= NND) return;
    const float* xr = &g_xt[(size_t)row * NHID];
    float acc[8] = {0, 0, 0, 0, 0, 0, 0, 0};
    for (int h = lane; h < NHID; h += 32) {
        float xv = xr[h];
        const float4* wp = reinterpret_cast<const float4*>(&W2[h * 8]);
        float4 wlo = wp[0], whi = wp[1];
        acc[0] = fmaf(xv, wlo.x, acc[0]);
        acc[1] = fmaf(xv, wlo.y, acc[1]);
        acc[2] = fmaf(xv, wlo.z, acc[2]);
        acc[3] = fmaf(xv, wlo.w, acc[3]);
        acc[4] = fmaf(xv, whi.x, acc[4]);
        acc[5] = fmaf(xv, whi.y, acc[5]);
        acc[6] = fmaf(xv, whi.z, acc[6]);
        acc[7] = fmaf(xv, whi.w, acc[7]);
    }
#pragma unroll
    for (int c = 0; c < 8; c++)
#pragma unroll
        for (int off = 16; off; off >>= 1) acc[c] += __shfl_down_sync(0xffffffffu, acc[c], off);
    if (lane == 0) {
#pragma unroll
        for (int c = 0; c < 8; c++) g_xtw2[row * 8 + c] = acc[c];
    }
}

// ---------------- z = adj @ xtw2 + b2 ; out = softmax(z). 8 rows/CTA ----
__global__ void final_k(const float* __restrict__ b2, float* __restrict__ out) {
    const int r0  = blockIdx.x * 8;
    const int tid = threadIdx.x;
    float acc[8][8];
#pragma unroll
    for (int r = 0; r < 8; r++)
#pragma unroll
        for (int c = 0; c < 8; c++) acc[r][c] = 0.f;

    for (int j4 = tid; j4 < NND / 4; j4 += 256) {
        float4 w[8];
        const float4* wp = reinterpret_cast<const float4*>(&g_xtw2[(size_t)j4 * 32]);
#pragma unroll
        for (int q = 0; q < 8; q++) w[q] = wp[q];
#pragma unroll
        for (int r = 0; r < 8; r++) {
            float4 a = *reinterpret_cast<const float4*>(&g_adj[(size_t)(r0 + r) * NND + j4 * 4]);
            float av[4] = {a.x, a.y, a.z, a.w};
#pragma unroll
            for (int q = 0; q < 4; q++) {
                acc[r][0] = fmaf(av[q], w[2 * q].x, acc[r][0]);
                acc[r][1] = fmaf(av[q], w[2 * q].y, acc[r][1]);
                acc[r][2] = fmaf(av[q], w[2 * q].z, acc[r][2]);
                acc[r][3] = fmaf(av[q], w[2 * q].w, acc[r][3]);
                acc[r][4] = fmaf(av[q], w[2 * q + 1].x, acc[r][4]);
                acc[r][5] = fmaf(av[q], w[2 * q + 1].y, acc[r][5]);
                acc[r][6] = fmaf(av[q], w[2 * q + 1].z, acc[r][6]);
                acc[r][7] = fmaf(av[q], w[2 * q + 1].w, acc[r][7]);
            }
        }
    }

    __shared__ float sred[8][64];
    const int lane = tid & 31, warp = tid >> 5;
#pragma unroll
    for (int r = 0; r < 8; r++)
#pragma unroll
        for (int c = 0; c < 8; c++) {
            float vv = acc[r][c];
#pragma unroll
            for (int off = 16; off; off >>= 1) vv += __shfl_down_sync(0xffffffffu, vv, off);
            if (lane == 0) sred[warp][r * 8 + c] = vv;
        }
    __syncthreads();
    if (tid < 64) {
        float v = 0.f;
#pragma unroll
        for (int w = 0; w < 8; w++) v += sred[w][tid];
        int c = tid & 7;
        v += b2[c];
        float mx = v;
#pragma unroll
        for (int off = 4; off; off >>= 1) mx = fmaxf(mx, __shfl_xor_sync(0xffffffffu, mx, off, 8));
        float e = expf(v - mx);
        float s = e;
#pragma unroll
        for (int off = 4; off; off >>= 1) s += __shfl_xor_sync(0xffffffffu, s, off, 8);
        out[(size_t)(r0 + (tid >> 3)) * 8 + c] = e / s;
    }
}

// ---------------- host side ----------------
template <typename T>
static T* symaddr(const void* sym) {
    void* p = nullptr;
    cudaGetSymbolAddress(&p, sym);
    return (T*)p;
}

extern "C" void kernel_launch(void* const* d_in, const int* in_sizes, int n_in,
                              void* d_out, int out_size) {
    const float* adj0 = (const float*)d_in[0];
    const float* adj1 = (const float*)d_in[1];
    const float* adj2 = (const float*)d_in[2];
    const float* feats = (const float*)d_in[3];
    const float* Wa1 = (const float*)d_in[4];
    const float* ba1 = (const float*)d_in[5];
    const float* Wa2 = (const float*)d_in[6];
    const float* ba2 = (const float*)d_in[7];
    const float* Wa3 = (const float*)d_in[8];
    const float* ba3 = (const float*)d_in[9];
    const float* Wagg = (const float*)d_in[10];
    const float* bagg = (const float*)d_in[11];
    const float* W1 = (const float*)d_in[12];
    const float* b1 = (const float*)d_in[13];
    const float* Wq = (const float*)d_in[14];
    const float* bq = (const float*)d_in[15];
    const float* Wk = (const float*)d_in[16];
    const float* bk = (const float*)d_in[17];
    const float* Wv = (const float*)d_in[18];
    const float* bv = (const float*)d_in[19];
    const float* W2 = (const float*)d_in[20];
    const float* b2 = (const float*)d_in[21];
    float* out = (float*)d_out;

    float* adjp  = symaddr<float>(g_adj);
    float* attp  = symaddr<float>(g_att);
    float* partp = symaddr<float>(g_part);
    float* xtp   = symaddr<float>(g_xt);
    bf16* adjH = symaddr<bf16>(g_adjH);   bf16* adjL = symaddr<bf16>(g_adjL);
    bf16* attH = symaddr<bf16>(g_attH);   bf16* attL = symaddr<bf16>(g_attL);
    bf16* ftH  = symaddr<bf16>(g_featsH); bf16* ftL  = symaddr<bf16>(g_featsL);
    bf16* W1TH = symaddr<bf16>(g_W1TH);   bf16* W1TL = symaddr<bf16>(g_W1TL);
    bf16* WqTH = symaddr<bf16>(g_WqTH);   bf16* WqTL = symaddr<bf16>(g_WqTL);
    bf16* WkTH = symaddr<bf16>(g_WkTH);   bf16* WkTL = symaddr<bf16>(g_WkTL);
    bf16* WvTH = symaddr<bf16>(g_WvTH);   bf16* WvTL = symaddr<bf16>(g_WvTL);
    bf16* fW1TH = symaddr<bf16>(g_fW1TH); bf16* fW1TL = symaddr<bf16>(g_fW1TL);
    bf16* xH   = symaddr<bf16>(g_xH);     bf16* xL   = symaddr<bf16>(g_xL);
    bf16* QH   = symaddr<bf16>(g_QH);     bf16* QL   = symaddr<bf16>(g_QL);
    bf16* KHp  = symaddr<bf16>(g_KHb);    bf16* KLp  = symaddr<bf16>(g_KLb);
    bf16* VTH  = symaddr<bf16>(g_VTH);    bf16* VTL  = symaddr<bf16>(g_VTL);

    cudaFuncSetAttribute(mma_gemm, cudaFuncAttributeMaxDynamicSharedMemorySize, GSMEM);

    int write_nz = (out_size >= NND * (NCLASS + 3)) ? 1 : 0;
    const size_t PS = (size_t)NND * NHID;

    // 0: feats split
    split_k<<<592, 256>>>(feats, ftH, ftL, NND * NFEAT / 4);
    // 1: W1 transpose+split
    {
        TSArgs t{};
        t.in[0] = W1; t.oH[0] = W1TH; t.oL[0] = W1TL; t.R = NFEAT; t.C = NHID;
        transpose_split_k<<<dim3(NHID / 32, NFEAT / 32, 1), dim3(32, 8)>>>(t);
    }
    // 2: fold
    fold_k<<<dim3(NND / 128, 3), 128>>>(Wa1, Wa2, Wa3, Wagg, bagg, ba1, ba2, ba3);

    // 3: L4: fW1^T(split) = (feats @ W1)^T   <-- profiled launch
    {
        GArgs a{};
        a.AH[0] = ftH; a.AL[0] = ftL;
        a.BH[0] = W1TH; a.BL[0] = W1TL;
        a.CH[0] = fW1TH; a.CL[0] = fW1TL;
        a.M = NND; a.N = NHID; a.K = NFEAT; a.lda = NFEAT; a.ldb = NFEAT; a.ldc = NHID;
        a.estore[0] = 3;
        mma_gemm<<<dim3(48, 2, 1), 256, GSMEM>>>(a);
    }

    // 4: gemv + gate softmax -> nz
    gemv_nz_k<<<NND / GV_ROWS, 256>>>(adj0, adj1, adj2, out + (size_t)NND * NCLASS, write_nz);
    // 5: Wq/Wk/Wv transpose+split (batched)
    {
        TSArgs t{};
        t.in[0] = Wq; t.in[1] = Wk; t.in[2] = Wv;
        t.oH[0] = WqTH; t.oH[1] = WkTH; t.oH[2] = WvTH;
        t.oL[0] = WqTL; t.oL[1] = WkTL; t.oL[2] = WvTL;
        t.R = NHID; t.C = NHID;
        transpose_split_k<<<dim3(NHID / 32, NHID / 32, 3), dim3(32, 8)>>>(t);
    }
    // 6: fused adjacency (fp32 + split)
    build_adj_k<<<1184, 256>>>(adj0, adj1, adj2);

    // 7: L5 split-K: partials of adj @ fW1
    {
        GArgs a{};
        a.AH[0] = adjH; a.AL[0] = adjL;
        a.BH[0] = fW1TH; a.BL[0] = fW1TL;
        a.C[0] = partp; a.C[1] = partp + PS; a.C[2] = partp + 2 * PS;
        a.M = NND; a.N = NHID; a.K = NND; a.lda = NND; a.ldb = NND; a.ldc = NHID;
        a.kLen = NND / 3;
        a.estore[0] = a.estore[1] = a.estore[2] = 0;
        mma_gemm<<<dim3(48, 2, 3), 256, GSMEM>>>(a);
    }
    // 8: reduce -> x (split)
    reduce_split_k<<<1536, 256>>>(b1, xH, xL);

    // 9: L6: Q,K (split); V (split transposed)
    {
        GArgs a{};
        a.AH[0] = a.AH[1] = a.AH[2] = xH;
        a.AL[0] = a.AL[1] = a.AL[2] = xL;
        a.BH[0] = WqTH; a.BH[1] = WkTH; a.BH[2] = WvTH;
        a.BL[0] = WqTL; a.BL[1] = WkTL; a.BL[2] = WvTL;
        a.CH[0] = QH; a.CL[0] = QL;
        a.CH[1] = KHp; a.CL[1] = KLp;
        a.CH[2] = VTH; a.CL[2] = VTL;
        a.bias[0] = bq; a.bias[1] = bk; a.bias[2] = bv;
        a.M = NND; a.N = NHID; a.K = NHID; a.lda = NHID; a.ldb = NHID; a.ldc = NHID;
        a.estore[0] = 2; a.estore[1] = 2; a.estore[2] = 3;
        mma_gemm<<<dim3(48, 2, 3), 256, GSMEM>>>(a);
    }

    // 10: L7: A_tilde = adj * (Q @ K^T)  (fp32 logits)
    {
        GArgs a{};
        a.AH[0] = QH; a.AL[0] = QL;
        a.BH[0] = KHp; a.BL[0] = KLp;
        a.C[0] = attp;
        a.mul = adjp;
        a.M = NND; a.N = NND; a.K = NHID; a.lda = NHID; a.ldb = NHID; a.ldc = NND;
        a.estore[0] = 0;
        mma_gemm<<<dim3(48, 48, 1), 256, GSMEM>>>(a);
    }

    // 11: row softmax -> att split
    attn_softmax_k<<<NND, 256>>>();

    // 12: L9 split-K: partials of attention @ V
    {
        GArgs a{};
        a.AH[0] = attH; a.AL[0] = attL;
        a.BH[0] = VTH; a.BL[0] = VTL;
        a.C[0] = partp; a.C[1] = partp + PS; a.C[2] = partp + 2 * PS;
        a.M = NND; a.N = NHID; a.K = NND; a.lda = NND; a.ldb = NND; a.ldc = NHID;
        a.kLen = NND / 3;
        a.estore[0] = a.estore[1] = a.estore[2] = 0;
        mma_gemm<<<dim3(48, 2, 3), 256, GSMEM>>>(a);
    }
    // 13: reduce -> xt (fp32, relu)
    reduce_f32_k<<<1536, 256>>>(xtp);

    // 14, 15
    xtw2_k<<<768, 256>>>(W2);
    final_k<<<768, 256>>>(b2, out);
}

// round 9
// speedup vs baseline: 1.1891x; 1.0013x over previous
#include <cuda_runtime.h>
#include <cuda_bf16.h>
#include <math.h>
#include <stdint.h>

#define NND    6144
#define NFEAT  512
#define NHID   256
#define NCLASS 8
#define ADIM   128

typedef __nv_bfloat16 bf16;

// ---------------- device scratch (no allocations allowed) ----------------
__device__ float g_nzT[3 * NND];
__device__ float g_wfold[3 * NND * 4];
__device__ float g_bfold[3];
__device__ float g_adj[(size_t)NND * NND];
__device__ float g_att[(size_t)NND * NND];
__device__ float g_part[3 * (size_t)NND * NHID];
__device__ float g_xt[(size_t)NND * NHID];
__device__ float g_xtw2[NND * NCLASS];

__device__ bf16 g_adjH[(size_t)NND * NND],   g_adjL[(size_t)NND * NND];
__device__ bf16 g_attH[(size_t)NND * NND],   g_attL[(size_t)NND * NND];
__device__ bf16 g_featsH[(size_t)NND * NFEAT], g_featsL[(size_t)NND * NFEAT];
__device__ bf16 g_W1TH[NHID * NFEAT],  g_W1TL[NHID * NFEAT];
__device__ bf16 g_WqTH[NHID * NHID],   g_WqTL[NHID * NHID];
__device__ bf16 g_WkTH[NHID * NHID],   g_WkTL[NHID * NHID];
__device__ bf16 g_WvTH[NHID * NHID],   g_WvTL[NHID * NHID];
__device__ bf16 g_fW1TH[(size_t)NHID * NND], g_fW1TL[(size_t)NHID * NND];
__device__ bf16 g_xH[(size_t)NND * NHID],  g_xL[(size_t)NND * NHID];
__device__ bf16 g_QH[(size_t)NND * NHID],  g_QL[(size_t)NND * NHID];
__device__ bf16 g_KHb[(size_t)NND * NHID], g_KLb[(size_t)NND * NHID];
__device__ bf16 g_VTH[(size_t)NHID * NND], g_VTL[(size_t)NHID * NND];

// ---------------- helpers ----------------
__device__ __forceinline__ uint32_t s2u(const void* p) {
    uint32_t a;
    asm("{ .reg .u64 t; cvta.to.shared.u64 t, %1; cvt.u32.u64 %0, t; }" : "=r"(a) : "l"(p));
    return a;
}
__device__ __forceinline__ void split1(float v, bf16& h, bf16& l) {
    h = __float2bfloat16(v);
    l = __float2bfloat16(v - __bfloat162float(h));
}
__device__ __forceinline__ void cvt_split2(float x, float y, uint32_t& hi, uint32_t& lo) {
    __nv_bfloat162 h = __float22bfloat162_rn(make_float2(x, y));
    hi = *reinterpret_cast<uint32_t*>(&h);
    float hx = __uint_as_float(hi << 16);
    float hy = __uint_as_float(hi & 0xFFFF0000u);
    __nv_bfloat162 l = __float22bfloat162_rn(make_float2(x - hx, y - hy));
    lo = *reinterpret_cast<uint32_t*>(&l);
}
__device__ __forceinline__ void split4(float4 v, uint2& h, uint2& l) {
    cvt_split2(v.x, v.y, h.x, l.x);
    cvt_split2(v.z, v.w, h.y, l.y);
}

#define LDSM4(r, a)                                                                        \
    asm volatile("ldmatrix.sync.aligned.m8n8.x4.shared.b16 {%0,%1,%2,%3}, [%4];"           \
                 : "=r"((r)[0]), "=r"((r)[1]), "=r"((r)[2]), "=r"((r)[3]) : "r"(a))
#define LDSM2(r, a)                                                                        \
    asm volatile("ldmatrix.sync.aligned.m8n8.x2.shared.b16 {%0,%1}, [%2];"                 \
                 : "=r"((r)[0]), "=r"((r)[1]) : "r"(a))

__device__ __forceinline__ void mma16816(float c[4], const uint32_t a[4], const uint32_t b[2]) {
    asm volatile(
        "mma.sync.aligned.m16n8k16.row.col.f32.bf16.bf16.f32 "
        "{%0,%1,%2,%3}, {%4,%5,%6,%7}, {%8,%9}, {%0,%1,%2,%3};"
        : "+f"(c[0]), "+f"(c[1]), "+f"(c[2]), "+f"(c[3])
        : "r"(a[0]), "r"(a[1]), "r"(a[2]), "r"(a[3]), "r"(b[0]), "r"(b[1]));
}

// ---------------- GEMM: C = act((A @ B'^T) * mul + bias) ----------------
// A,B pre-split bf16 H/L. Tile 128x128, 512 threads / 16 warps (4x4 grid),
// warp tile 32x32, KC=32/iter. 3-term split Ah*Bh + Ah*Bl + Al*Bh, fp32 acc.
struct GArgs {
    const bf16* AH[3]; const bf16* AL[3];
    const bf16* BH[3]; const bf16* BL[3];
    float* C[3];
    bf16* CH[3]; bf16* CL[3];
    const float* bias[3];
    const float* mul;
    int M, N, K, lda, ldb, ldc, act;
    int kLen;            // 0: bz = batch index; else bz = K-chunk index
    int estore[3];       // 0 fp32, 2 split, 3 split transposed
};

#define ROWB 80
#define TILEB (128 * ROWB)
#define STAGEB (4 * TILEB)
#define GSMEM (2 * STAGEB)

__global__ void __launch_bounds__(512, 1) mma_gemm(const GArgs p) {
    extern __shared__ __align__(16) char smem[];

    const int bz = blockIdx.z;
    const int bi = p.kLen ? 0 : bz;
    const int kOff = p.kLen ? bz * p.kLen : 0;
    const int Kloc = p.kLen ? p.kLen : p.K;

    const int m0 = blockIdx.x * 128, n0 = blockIdx.y * 128;
    const int lda = p.lda, ldb = p.ldb, ldc = p.ldc;

    const bf16* __restrict__ pAH = p.AH[bi] + (size_t)m0 * lda + kOff;
    const bf16* __restrict__ pAL = p.AL[bi] + (size_t)m0 * lda + kOff;
    const bf16* __restrict__ pBH = p.BH[bi] + (size_t)n0 * ldb + kOff;
    const bf16* __restrict__ pBL = p.BL[bi] + (size_t)n0 * ldb + kOff;
    const float* __restrict__ bias = p.bias[bi];

    const int tid  = threadIdx.x;
    const int lane = tid & 31, wid = tid >> 5;
    const int wm = wid & 3, wn = wid >> 2;     // 4x4 warp grid, 32x32 warp tiles

    const uint32_t u0 = s2u(smem);
    const uint32_t aRowOff = (uint32_t)((lane & 15) * ROWB + ((lane & 16) ? 16 : 0));
    const uint32_t bRowOff = (uint32_t)((lane & 7) * ROWB + ((lane & 8) ? 16 : 0));

    float acc[2][4][4];
#pragma unroll
    for (int mt = 0; mt < 2; mt++)
#pragma unroll
        for (int nt = 0; nt < 4; nt++)
#pragma unroll
            for (int q = 0; q < 4; q++) acc[mt][nt][q] = 0.f;

    uint4 rah, ral, rbh, rbl;

    // per-thread fill: 512 threads, 1 x 16B chunk per tile per stage
    const int fRow = tid >> 2;
    const int fC8  = (tid & 3) << 3;
    const int fOff = fRow * ROWB + ((tid & 3) << 4);
    auto loadT = [&](int k0) {
        rah = *reinterpret_cast<const uint4*>(pAH + (size_t)fRow * lda + k0 + fC8);
        ral = *reinterpret_cast<const uint4*>(pAL + (size_t)fRow * lda + k0 + fC8);
        rbh = *reinterpret_cast<const uint4*>(pBH + (size_t)fRow * ldb + k0 + fC8);
        rbl = *reinterpret_cast<const uint4*>(pBL + (size_t)fRow * ldb + k0 + fC8);
    };
    auto storeT = [&](int stage) {
        char* AHs = smem + stage * STAGEB;
        *reinterpret_cast<uint4*>(AHs + fOff) = rah;
        *reinterpret_cast<uint4*>(AHs + TILEB + fOff) = ral;
        *reinterpret_cast<uint4*>(AHs + 2 * TILEB + fOff) = rbh;
        *reinterpret_cast<uint4*>(AHs + 3 * TILEB + fOff) = rbl;
    };
    auto compute = [&](int stage) {
        const uint32_t uAH = u0 + (uint32_t)(stage * STAGEB);
        const uint32_t uAL = uAH + TILEB;
        const uint32_t uBH = uAL + TILEB;
        const uint32_t uBL = uBH + TILEB;
#pragma unroll
        for (int ks = 0; ks < 2; ks++) {
            const uint32_t ka = (uint32_t)(ks * 32);
            uint32_t ah[2][4], bh[4][2], bl[4][2];
#pragma unroll
            for (int mt = 0; mt < 2; mt++)
                LDSM4(ah[mt], uAH + (uint32_t)((wm * 32 + mt * 16) * ROWB) + aRowOff + ka);
#pragma unroll
            for (int nt = 0; nt < 4; nt++) {
                uint32_t ro = (uint32_t)((wn * 32 + nt * 8) * ROWB) + bRowOff + ka;
                LDSM2(bh[nt], uBH + ro);
                LDSM2(bl[nt], uBL + ro);
            }
#pragma unroll
            for (int mt = 0; mt < 2; mt++)
#pragma unroll
                for (int nt = 0; nt < 4; nt++) mma16816(acc[mt][nt], ah[mt], bh[nt]);
#pragma unroll
            for (int mt = 0; mt < 2; mt++)
#pragma unroll
                for (int nt = 0; nt < 4; nt++) mma16816(acc[mt][nt], ah[mt], bl[nt]);
#pragma unroll
            for (int mt = 0; mt < 2; mt++) {
                uint32_t alf[4];
                LDSM4(alf, uAL + (uint32_t)((wm * 32 + mt * 16) * ROWB) + aRowOff + ka);
#pragma unroll
                for (int nt = 0; nt < 4; nt++) mma16816(acc[mt][nt], alf, bh[nt]);
            }
        }
    };

    const int niter = Kloc >> 5;
    loadT(0);
    storeT(0);
    if (niter > 1) loadT(32);
    __syncthreads();
    for (int i = 0; i < niter; i++) {
        if (i + 1 < niter) storeT((i + 1) & 1);
        if (i + 2 < niter) loadT((i + 2) << 5);
        compute(i & 1);
        __syncthreads();
    }

    // ---------------- epilogue ----------------
    const int es = p.estore[bz];
    float* __restrict__ C  = p.C[bz];
    bf16* __restrict__ CH = p.CH[bz];
    bf16* __restrict__ CL = p.CL[bz];
    const float* __restrict__ mul = p.mul;
#pragma unroll
    for (int mt = 0; mt < 2; mt++) {
#pragma unroll
        for (int nt = 0; nt < 4; nt++) {
            int mA = m0 + wm * 32 + mt * 16 + (lane >> 2);
            int n  = n0 + wn * 32 + nt * 8 + 2 * (lane & 3);
#pragma unroll
            for (int h = 0; h < 2; h++) {
                int mm = mA + h * 8;
                float vx = acc[mt][nt][2 * h + 0];
                float vy = acc[mt][nt][2 * h + 1];
                if (mul) {
                    float2 mv = *reinterpret_cast<const float2*>(&mul[(size_t)mm * ldc + n]);
                    vx *= mv.x; vy *= mv.y;
                }
                if (bias) { vx += bias[n]; vy += bias[n + 1]; }
                if (p.act) { vx = fmaxf(vx, 0.f); vy = fmaxf(vy, 0.f); }
                if (es == 0) {
                    *reinterpret_cast<float2*>(&C[(size_t)mm * ldc + n]) = make_float2(vx, vy);
                } else if (es == 2) {
                    uint32_t hi, lo;
                    cvt_split2(vx, vy, hi, lo);
                    *reinterpret_cast<uint32_t*>(&CH[(size_t)mm * ldc + n]) = hi;
                    *reinterpret_cast<uint32_t*>(&CL[(size_t)mm * ldc + n]) = lo;
                } else {  // 3: split transposed
                    bf16 hx, lx, hy, ly;
                    split1(vx, hx, lx);
                    split1(vy, hy, ly);
                    CH[(size_t)n * p.M + mm] = hx;
                    CL[(size_t)n * p.M + mm] = lx;
                    CH[(size_t)(n + 1) * p.M + mm] = hy;
                    CL[(size_t)(n + 1) * p.M + mm] = ly;
                }
            }
        }
    }
}

// ---- split-K reduce: x = relu(sum part + bias) -> bf16 H/L ----
__global__ void reduce_split_k(const float* __restrict__ bias, bf16* __restrict__ oH,
                               bf16* __restrict__ oL) {
    const int n4 = NND * NHID / 4;
    const size_t S = (size_t)NND * NHID;
    for (int e = blockIdx.x * blockDim.x + threadIdx.x; e < n4; e += gridDim.x * blockDim.x) {
        float4 a = reinterpret_cast<const float4*>(g_part)[e];
        float4 b = reinterpret_cast<const float4*>(g_part + S)[e];
        float4 c = reinterpret_cast<const float4*>(g_part + 2 * S)[e];
        int col = (e * 4) & (NHID - 1);
        float4 v;
        v.x = fmaxf(a.x + b.x + c.x + bias[col + 0], 0.f);
        v.y = fmaxf(a.y + b.y + c.y + bias[col + 1], 0.f);
        v.z = fmaxf(a.z + b.z + c.z + bias[col + 2], 0.f);
        v.w = fmaxf(a.w + b.w + c.w + bias[col + 3], 0.f);
        uint2 h, l;
        split4(v, h, l);
        reinterpret_cast<uint2*>(oH)[e] = h;
        reinterpret_cast<uint2*>(oL)[e] = l;
    }
}
// ---- split-K reduce: xt = relu(sum part) -> fp32 ----
__global__ void reduce_f32_k(float* __restrict__ o) {
    const int n4 = NND * NHID / 4;
    const size_t S = (size_t)NND * NHID;
    for (int e = blockIdx.x * blockDim.x + threadIdx.x; e < n4; e += gridDim.x * blockDim.x) {
        float4 a = reinterpret_cast<const float4*>(g_part)[e];
        float4 b = reinterpret_cast<const float4*>(g_part + S)[e];
        float4 c = reinterpret_cast<const float4*>(g_part + 2 * S)[e];
        float4 v;
        v.x = fmaxf(a.x + b.x + c.x, 0.f);
        v.y = fmaxf(a.y + b.y + c.y, 0.f);
        v.z = fmaxf(a.z + b.z + c.z, 0.f);
        v.w = fmaxf(a.w + b.w + c.w, 0.f);
        reinterpret_cast<float4*>(o)[e] = v;
    }
}

// ---------------- transpose + split ----------------
struct TSArgs {
    const float* in[3];
    bf16* oH[3]; bf16* oL[3];
    int R, C;
};
__global__ void transpose_split_k(const TSArgs p) {
    __shared__ float t[32][33];
    const float* __restrict__ in = p.in[blockIdx.z];
    bf16* __restrict__ oH = p.oH[blockIdx.z];
    bf16* __restrict__ oL = p.oL[blockIdx.z];
    const int R = p.R, C = p.C;
    int c0 = blockIdx.x * 32, r0 = blockIdx.y * 32;
    int x = threadIdx.x, y = threadIdx.y;
#pragma unroll
    for (int i = 0; i < 32; i += 8) t[y + i][x] = in[(size_t)(r0 + y + i) * C + c0 + x];
    __syncthreads();
#pragma unroll
    for (int i = 0; i < 32; i += 8) {
        float v = t[x][y + i];
        bf16 h, l;
        split1(v, h, l);
        oH[(size_t)(c0 + y + i) * R + r0 + x] = h;
        oL[(size_t)(c0 + y + i) * R + r0 + x] = l;
    }
}

// ---------------- elementwise split ----------------
__global__ void split_k(const float* __restrict__ in, bf16* __restrict__ oH,
                        bf16* __restrict__ oL, int n4) {
    for (int e = blockIdx.x * blockDim.x + threadIdx.x; e < n4; e += gridDim.x * blockDim.x) {
        float4 v = reinterpret_cast<const float4*>(in)[e];
        uint2 h, l;
        split4(v, h, l);
        reinterpret_cast<uint2*>(oH)[e] = h;
        reinterpret_cast<uint2*>(oL)[e] = l;
    }
}

// ---- fold: Wfold[l][j][c] = sum_k Wa_l[j,k] * Wagg[l*128+k, c]; bfold = ba@Wagg+bagg
__global__ void fold_k(const float* __restrict__ Wa1, const float* __restrict__ Wa2,
                       const float* __restrict__ Wa3, const float* __restrict__ Wagg,
                       const float* __restrict__ bagg, const float* __restrict__ ba1,
                       const float* __restrict__ ba2, const float* __restrict__ ba3) {
    int j = blockIdx.x * 128 + threadIdx.x;
    int l = blockIdx.y;
    const float* Wa = (l == 0) ? Wa1 : (l == 1) ? Wa2 : Wa3;
    float c0 = 0.f, c1 = 0.f, c2 = 0.f;
    for (int k = 0; k < ADIM; k++) {
        float a = Wa[(size_t)j * ADIM + k];
        const float* wg = &Wagg[(l * ADIM + k) * 3];
        c0 = fmaf(a, wg[0], c0);
        c1 = fmaf(a, wg[1], c1);
        c2 = fmaf(a, wg[2], c2);
    }
    *reinterpret_cast<float4*>(&g_wfold[((size_t)l * NND + j) * 4]) =
        make_float4(c0, c1, c2, 0.f);
    if (blockIdx.x == 0 && l == 0 && threadIdx.x < 3) {
        int c = threadIdx.x;
        float b = bagg[c];
        for (int k = 0; k < ADIM; k++) {
            b += ba1[k] * Wagg[k * 3 + c];
            b += ba2[k] * Wagg[(ADIM + k) * 3 + c];
            b += ba3[k] * Wagg[(2 * ADIM + k) * 3 + c];
        }
        g_bfold[c] = b;
    }
}

// ---- gemv+gate: z4[r,c] = sum_l sum_j adj_l[r,j]*Wfold[l][j][c] + bfold; nz=softmax
#define GV_ROWS 32
#define GV_CH 512
__global__ void gemv_nz_k(const float* __restrict__ a0, const float* __restrict__ a1,
                          const float* __restrict__ a2, float* __restrict__ out_nz,
                          int write_out) {
    __shared__ float sw[9 * GV_CH];
    const int tid = threadIdx.x;
    const int lane = tid & 31, warp = tid >> 5;
    const int rbase = blockIdx.x * GV_ROWS + warp * 4;
    float s[4][3];
#pragma unroll
    for (int r = 0; r < 4; r++)
#pragma unroll
        for (int c = 0; c < 3; c++) s[r][c] = 0.f;

    for (int ch = 0; ch < NND; ch += GV_CH) {
        __syncthreads();
        for (int idx = tid; idx < 3 * GV_CH; idx += 256) {
            int l = idx / GV_CH, j = idx % GV_CH;
            float4 w = *reinterpret_cast<const float4*>(&g_wfold[((size_t)l * NND + ch + j) * 4]);
            sw[(l * 3 + 0) * GV_CH + j] = w.x;
            sw[(l * 3 + 1) * GV_CH + j] = w.y;
            sw[(l * 3 + 2) * GV_CH + j] = w.z;
        }
        __syncthreads();
        for (int j = lane; j < GV_CH; j += 32) {
            float w00 = sw[0 * GV_CH + j], w01 = sw[1 * GV_CH + j], w02 = sw[2 * GV_CH + j];
            float w10 = sw[3 * GV_CH + j], w11 = sw[4 * GV_CH + j], w12 = sw[5 * GV_CH + j];
            float w20 = sw[6 * GV_CH + j], w21 = sw[7 * GV_CH + j], w22 = sw[8 * GV_CH + j];
#pragma unroll
            for (int r = 0; r < 4; r++) {
                size_t off = (size_t)(rbase + r) * NND + ch + j;
                float v0 = a0[off], v1 = a1[off], v2 = a2[off];
                s[r][0] += v0 * w00 + v1 * w10 + v2 * w20;
                s[r][1] += v0 * w01 + v1 * w11 + v2 * w21;
                s[r][2] += v0 * w02 + v1 * w12 + v2 * w22;
            }
        }
    }
#pragma unroll
    for (int r = 0; r < 4; r++)
#pragma unroll
        for (int c = 0; c < 3; c++) {
            float v = s[r][c];
#pragma unroll
            for (int off = 16; off; off >>= 1) v += __shfl_down_sync(0xffffffffu, v, off);
            s[r][c] = v;
        }
    if (lane == 0) {
#pragma unroll
        for (int r = 0; r < 4; r++) {
            int row = rbase + r;
            float z0 = s[r][0] + g_bfold[0];
            float z1 = s[r][1] + g_bfold[1];
            float z2 = s[r][2] + g_bfold[2];
            float mx = fmaxf(z0, fmaxf(z1, z2));
            float e0 = expf(z0 - mx), e1 = expf(z1 - mx), e2 = expf(z2 - mx);
            float inv = 1.f / (e0 + e1 + e2);
            e0 *= inv; e1 *= inv; e2 *= inv;
            g_nzT[0 * NND + row] = e0;
            g_nzT[1 * NND + row] = e1;
            g_nzT[2 * NND + row] = e2;
            if (write_out) {
                out_nz[row * 3 + 0] = e0;
                out_nz[row * 3 + 1] = e1;
                out_nz[row * 3 + 2] = e2;
            }
        }
    }
}

// ---- adj = col-weighted mix; emit fp32 + bf16 split ----
__global__ void build_adj_k(const float* __restrict__ a0, const float* __restrict__ a1,
                            const float* __restrict__ a2) {
    const size_t total4 = (size_t)NND * NND / 4;
    for (size_t e = (size_t)blockIdx.x * blockDim.x + threadIdx.x; e < total4;
         e += (size_t)gridDim.x * blockDim.x) {
        size_t off = e * 4;
        int j = (int)(off % NND);
        float4 w0 = *reinterpret_cast<const float4*>(&g_nzT[j]);
        float4 w1 = *reinterpret_cast<const float4*>(&g_nzT[NND + j]);
        float4 w2 = *reinterpret_cast<const float4*>(&g_nzT[2 * NND + j]);
        float4 x0 = *reinterpret_cast<const float4*>(a0 + off);
        float4 x1 = *reinterpret_cast<const float4*>(a1 + off);
        float4 x2 = *reinterpret_cast<const float4*>(a2 + off);
        float4 r;
        r.x = w0.x * x0.x + w1.x * x1.x + w2.x * x2.x;
        r.y = w0.y * x0.y + w1.y * x1.y + w2.y * x2.y;
        r.z = w0.z * x0.z + w1.z * x1.z + w2.z * x2.z;
        r.w = w0.w * x0.w + w1.w * x1.w + w2.w * x2.w;
        *reinterpret_cast<float4*>(&g_adj[off]) = r;
        uint2 h, l;
        split4(r, h, l);
        *reinterpret_cast<uint2*>(&g_adjH[off]) = h;
        *reinterpret_cast<uint2*>(&g_adjL[off]) = l;
    }
}

// ---- per-row softmax over 6144-wide fp32 logits; emit bf16 split ----
__global__ void attn_softmax_k() {
    const int row = blockIdx.x;
    const float* __restrict__ ptr = &g_att[(size_t)row * NND];
    const int tid  = threadIdx.x;
    const int lane = tid & 31, warp = tid >> 5;
    float4 v[6];
    float mx = -3.4e38f;
#pragma unroll
    for (int l = 0; l < 6; l++) {
        v[l] = *reinterpret_cast<const float4*>(&ptr[(tid + l * 256) * 4]);
        mx = fmaxf(mx, fmaxf(fmaxf(v[l].x, v[l].y), fmaxf(v[l].z, v[l].w)));
    }
    __shared__ float sm[8], ss[8];
#pragma unroll
    for (int off = 16; off; off >>= 1) mx = fmaxf(mx, __shfl_xor_sync(0xffffffffu, mx, off));
    if (lane == 0) sm[warp] = mx;
    __syncthreads();
    float bm = fmaxf(fmaxf(fmaxf(sm[0], sm[1]), fmaxf(sm[2], sm[3])),
                     fmaxf(fmaxf(sm[4], sm[5]), fmaxf(sm[6], sm[7])));
    float sum = 0.f;
#pragma unroll
    for (int l = 0; l < 6; l++) {
        v[l].x = expf(v[l].x - bm);
        v[l].y = expf(v[l].y - bm);
        v[l].z = expf(v[l].z - bm);
        v[l].w = expf(v[l].w - bm);
        sum += v[l].x + v[l].y + v[l].z + v[l].w;
    }
#pragma unroll
    for (int off = 16; off; off >>= 1) sum += __shfl_xor_sync(0xffffffffu, sum, off);
    if (lane == 0) ss[warp] = sum;
    __syncthreads();
    float tot = ss[0] + ss[1] + ss[2] + ss[3] + ss[4] + ss[5] + ss[6] + ss[7];
    float scale = 1.f / tot;
#pragma unroll
    for (int l = 0; l < 6; l++) {
        v[l].x *= scale; v[l].y *= scale; v[l].z *= scale; v[l].w *= scale;
        uint2 h, lo;
        split4(v[l], h, lo);
        size_t off = (size_t)row * NND + (tid + l * 256) * 4;
        *reinterpret_cast<uint2*>(&g_attH[off]) = h;
        *reinterpret_cast<uint2*>(&g_attL[off]) = lo;
    }
}

// ---------------- X_tilde @ W2 (skinny, N=8) ----------------
__global__ void xtw2_k(const float* __restrict__ W2) {
    int row  = blockIdx.x * 8 + (threadIdx.x >> 5);
    int lane = threadIdx.x & 31;
    if (row >= NND) return;
    const float* xr = &g_xt[(size_t)row * NHID];
    float acc[8] = {0, 0, 0, 0, 0, 0, 0, 0};
    for (int h = lane; h < NHID; h += 32) {
        float xv = xr[h];
        const float4* wp = reinterpret_cast<const float4*>(&W2[h * 8]);
        float4 wlo = wp[0], whi = wp[1];
        acc[0] = fmaf(xv, wlo.x, acc[0]);
        acc[1] = fmaf(xv, wlo.y, acc[1]);
        acc[2] = fmaf(xv, wlo.z, acc[2]);
        acc[3] = fmaf(xv, wlo.w, acc[3]);
        acc[4] = fmaf(xv, whi.x, acc[4]);
        acc[5] = fmaf(xv, whi.y, acc[5]);
        acc[6] = fmaf(xv, whi.z, acc[6]);
        acc[7] = fmaf(xv, whi.w, acc[7]);
    }
#pragma unroll
    for (int c = 0; c < 8; c++)
#pragma unroll
        for (int off = 16; off; off >>= 1) acc[c] += __shfl_down_sync(0xffffffffu, acc[c], off);
    if (lane == 0) {
#pragma unroll
        for (int c = 0; c < 8; c++) g_xtw2[row * 8 + c] = acc[c];
    }
}

// ---------------- z = adj @ xtw2 + b2 ; out = softmax(z). 8 rows/CTA ----
__global__ void final_k(const float* __restrict__ b2, float* __restrict__ out) {
    const int r0  = blockIdx.x * 8;
    const int tid = threadIdx.x;
    float acc[8][8];
#pragma unroll
    for (int r = 0; r < 8; r++)
#pragma unroll
        for (int c = 0; c < 8; c++) acc[r][c] = 0.f;

    for (int j4 = tid; j4 < NND / 4; j4 += 256) {
        float4 w[8];
        const float4* wp = reinterpret_cast<const float4*>(&g_xtw2[(size_t)j4 * 32]);
#pragma unroll
        for (int q = 0; q < 8; q++) w[q] = wp[q];
#pragma unroll
        for (int r = 0; r < 8; r++) {
            float4 a = *reinterpret_cast<const float4*>(&g_adj[(size_t)(r0 + r) * NND + j4 * 4]);
            float av[4] = {a.x, a.y, a.z, a.w};
#pragma unroll
            for (int q = 0; q < 4; q++) {
                acc[r][0] = fmaf(av[q], w[2 * q].x, acc[r][0]);
                acc[r][1] = fmaf(av[q], w[2 * q].y, acc[r][1]);
                acc[r][2] = fmaf(av[q], w[2 * q].z, acc[r][2]);
                acc[r][3] = fmaf(av[q], w[2 * q].w, acc[r][3]);
                acc[r][4] = fmaf(av[q], w[2 * q + 1].x, acc[r][4]);
                acc[r][5] = fmaf(av[q], w[2 * q + 1].y, acc[r][5]);
                acc[r][6] = fmaf(av[q], w[2 * q + 1].z, acc[r][6]);
                acc[r][7] = fmaf(av[q], w[2 * q + 1].w, acc[r][7]);
            }
        }
    }

    __shared__ float sred[8][64];
    const int lane = tid & 31, warp = tid >> 5;
#pragma unroll
    for (int r = 0; r < 8; r++)
#pragma unroll
        for (int c = 0; c < 8; c++) {
            float vv = acc[r][c];
#pragma unroll
            for (int off = 16; off; off >>= 1) vv += __shfl_down_sync(0xffffffffu, vv, off);
            if (lane == 0) sred[warp][r * 8 + c] = vv;
        }
    __syncthreads();
    if (tid < 64) {
        float v = 0.f;
#pragma unroll
        for (int w = 0; w < 8; w++) v += sred[w][tid];
        int c = tid & 7;
        v += b2[c];
        float mx = v;
#pragma unroll
        for (int off = 4; off; off >>= 1) mx = fmaxf(mx, __shfl_xor_sync(0xffffffffu, mx, off, 8));
        float e = expf(v - mx);
        float s = e;
#pragma unroll
        for (int off = 4; off; off >>= 1) s += __shfl_xor_sync(0xffffffffu, s, off, 8);
        out[(size_t)(r0 + (tid >> 3)) * 8 + c] = e / s;
    }
}

// ---------------- host side ----------------
template <typename T>
static T* symaddr(const void* sym) {
    void* p = nullptr;
    cudaGetSymbolAddress(&p, sym);
    return (T*)p;
}

extern "C" void kernel_launch(void* const* d_in, const int* in_sizes, int n_in,
                              void* d_out, int out_size) {
    const float* adj0 = (const float*)d_in[0];
    const float* adj1 = (const float*)d_in[1];
    const float* adj2 = (const float*)d_in[2];
    const float* feats = (const float*)d_in[3];
    const float* Wa1 = (const float*)d_in[4];
    const float* ba1 = (const float*)d_in[5];
    const float* Wa2 = (const float*)d_in[6];
    const float* ba2 = (const float*)d_in[7];
    const float* Wa3 = (const float*)d_in[8];
    const float* ba3 = (const float*)d_in[9];
    const float* Wagg = (const float*)d_in[10];
    const float* bagg = (const float*)d_in[11];
    const float* W1 = (const float*)d_in[12];
    const float* b1 = (const float*)d_in[13];
    const float* Wq = (const float*)d_in[14];
    const float* bq = (const float*)d_in[15];
    const float* Wk = (const float*)d_in[16];
    const float* bk = (const float*)d_in[17];
    const float* Wv = (const float*)d_in[18];
    const float* bv = (const float*)d_in[19];
    const float* W2 = (const float*)d_in[20];
    const float* b2 = (const float*)d_in[21];
    float* out = (float*)d_out;

    float* adjp  = symaddr<float>(g_adj);
    float* attp  = symaddr<float>(g_att);
    float* partp = symaddr<float>(g_part);
    float* xtp   = symaddr<float>(g_xt);
    bf16* adjH = symaddr<bf16>(g_adjH);   bf16* adjL = symaddr<bf16>(g_adjL);
    bf16* attH = symaddr<bf16>(g_attH);   bf16* attL = symaddr<bf16>(g_attL);
    bf16* ftH  = symaddr<bf16>(g_featsH); bf16* ftL  = symaddr<bf16>(g_featsL);
    bf16* W1TH = symaddr<bf16>(g_W1TH);   bf16* W1TL = symaddr<bf16>(g_W1TL);
    bf16* WqTH = symaddr<bf16>(g_WqTH);   bf16* WqTL = symaddr<bf16>(g_WqTL);
    bf16* WkTH = symaddr<bf16>(g_WkTH);   bf16* WkTL = symaddr<bf16>(g_WkTL);
    bf16* WvTH = symaddr<bf16>(g_WvTH);   bf16* WvTL = symaddr<bf16>(g_WvTL);
    bf16* fW1TH = symaddr<bf16>(g_fW1TH); bf16* fW1TL = symaddr<bf16>(g_fW1TL);
    bf16* xH   = symaddr<bf16>(g_xH);     bf16* xL   = symaddr<bf16>(g_xL);
    bf16* QH   = symaddr<bf16>(g_QH);     bf16* QL   = symaddr<bf16>(g_QL);
    bf16* KHp  = symaddr<bf16>(g_KHb);    bf16* KLp  = symaddr<bf16>(g_KLb);
    bf16* VTH  = symaddr<bf16>(g_VTH);    bf16* VTL  = symaddr<bf16>(g_VTL);

    cudaFuncSetAttribute(mma_gemm, cudaFuncAttributeMaxDynamicSharedMemorySize, GSMEM);

    int write_nz = (out_size >= NND * (NCLASS + 3)) ? 1 : 0;
    const size_t PS = (size_t)NND * NHID;

    // 0: feats split
    split_k<<<592, 256>>>(feats, ftH, ftL, NND * NFEAT / 4);
    // 1: W1 transpose+split
    {
        TSArgs t{};
        t.in[0] = W1; t.oH[0] = W1TH; t.oL[0] = W1TL; t.R = NFEAT; t.C = NHID;
        transpose_split_k<<<dim3(NHID / 32, NFEAT / 32, 1), dim3(32, 8)>>>(t);
    }
    // 2: fold
    fold_k<<<dim3(NND / 128, 3), 128>>>(Wa1, Wa2, Wa3, Wagg, bagg, ba1, ba2, ba3);

    // 3: L4: fW1^T(split) = (feats @ W1)^T   <-- profiled launch
    {
        GArgs a{};
        a.AH[0] = ftH; a.AL[0] = ftL;
        a.BH[0] = W1TH; a.BL[0] = W1TL;
        a.CH[0] = fW1TH; a.CL[0] = fW1TL;
        a.M = NND; a.N = NHID; a.K = NFEAT; a.lda = NFEAT; a.ldb = NFEAT; a.ldc = NHID;
        a.estore[0] = 3;
        mma_gemm<<<dim3(48, 2, 1), 512, GSMEM>>>(a);
    }

    // 4: gemv + gate softmax -> nz
    gemv_nz_k<<<NND / GV_ROWS, 256>>>(adj0, adj1, adj2, out + (size_t)NND * NCLASS, write_nz);
    // 5: Wq/Wk/Wv transpose+split (batched)
    {
        TSArgs t{};
        t.in[0] = Wq; t.in[1] = Wk; t.in[2] = Wv;
        t.oH[0] = WqTH; t.oH[1] = WkTH; t.oH[2] = WvTH;
        t.oL[0] = WqTL; t.oL[1] = WkTL; t.oL[2] = WvTL;
        t.R = NHID; t.C = NHID;
        transpose_split_k<<<dim3(NHID / 32, NHID / 32, 3), dim3(32, 8)>>>(t);
    }
    // 6: fused adjacency (fp32 + split)
    build_adj_k<<<1184, 256>>>(adj0, adj1, adj2);

    // 7: L5 split-K: partials of adj @ fW1
    {
        GArgs a{};
        a.AH[0] = adjH; a.AL[0] = adjL;
        a.BH[0] = fW1TH; a.BL[0] = fW1TL;
        a.C[0] = partp; a.C[1] = partp + PS; a.C[2] = partp + 2 * PS;
        a.M = NND; a.N = NHID; a.K = NND; a.lda = NND; a.ldb = NND; a.ldc = NHID;
        a.kLen = NND / 3;
        a.estore[0] = a.estore[1] = a.estore[2] = 0;
        mma_gemm<<<dim3(48, 2, 3), 512, GSMEM>>>(a);
    }
    // 8: reduce -> x (split)
    reduce_split_k<<<1536, 256>>>(b1, xH, xL);

    // 9: L6: Q,K (split); V (split transposed)
    {
        GArgs a{};
        a.AH[0] = a.AH[1] = a.AH[2] = xH;
        a.AL[0] = a.AL[1] = a.AL[2] = xL;
        a.BH[0] = WqTH; a.BH[1] = WkTH; a.BH[2] = WvTH;
        a.BL[0] = WqTL; a.BL[1] = WkTL; a.BL[2] = WvTL;
        a.CH[0] = QH; a.CL[0] = QL;
        a.CH[1] = KHp; a.CL[1] = KLp;
        a.CH[2] = VTH; a.CL[2] = VTL;
        a.bias[0] = bq; a.bias[1] = bk; a.bias[2] = bv;
        a.M = NND; a.N = NHID; a.K = NHID; a.lda = NHID; a.ldb = NHID; a.ldc = NHID;
        a.estore[0] = 2; a.estore[1] = 2; a.estore[2] = 3;
        mma_gemm<<<dim3(48, 2, 3), 512, GSMEM>>>(a);
    }

    // 10: L7: A_tilde = adj * (Q @ K^T)  (fp32 logits)
    {
        GArgs a{};
        a.AH[0] = QH; a.AL[0] = QL;
        a.BH[0] = KHp; a.BL[0] = KLp;
        a.C[0] = attp;
        a.mul = adjp;
        a.M = NND; a.N = NND; a.K = NHID; a.lda = NHID; a.ldb = NHID; a.ldc = NND;
        a.estore[0] = 0;
        mma_gemm<<<dim3(48, 48, 1), 512, GSMEM>>>(a);
    }

    // 11: row softmax -> att split
    attn_softmax_k<<<NND, 256>>>();

    // 12: L9 split-K: partials of attention @ V
    {
        GArgs a{};
        a.AH[0] = attH; a.AL[0] = attL;
        a.BH[0] = VTH; a.BL[0] = VTL;
        a.C[0] = partp; a.C[1] = partp + PS; a.C[2] = partp + 2 * PS;
        a.M = NND; a.N = NHID; a.K = NND; a.lda = NND; a.ldb = NND; a.ldc = NHID;
        a.kLen = NND / 3;
        a.estore[0] = a.estore[1] = a.estore[2] = 0;
        mma_gemm<<<dim3(48, 2, 3), 512, GSMEM>>>(a);
    }
    // 13: reduce -> xt (fp32, relu)
    reduce_f32_k<<<1536, 256>>>(xtp);

    // 14, 15
    xtw2_k<<<768, 256>>>(W2);
    final_k<<<768, 256>>>(b2, out);
}

// round 10
// speedup vs baseline: 1.3654x; 1.1483x over previous
#include <cuda_runtime.h>
#include <cuda_bf16.h>
#include <math.h>
#include <stdint.h>

#define NND    6144
#define NFEAT  512
#define NHID   256
#define NCLASS 8
#define ADIM   128

typedef __nv_bfloat16 bf16;

// ---------------- device scratch (no allocations allowed) ----------------
__device__ float g_nzT[3 * NND];
__device__ float g_wfold[3 * NND * 4];
__device__ float g_bfold[3];
__device__ float g_att[(size_t)NND * NND];
__device__ float g_part[3 * (size_t)NND * NHID];
__device__ float g_xt[(size_t)NND * NHID];
__device__ float g_xtw2[NND * NCLASS];

__device__ bf16 g_adjH[(size_t)NND * NND],   g_adjL[(size_t)NND * NND];
__device__ bf16 g_attH[(size_t)NND * NND],   g_attL[(size_t)NND * NND];
__device__ bf16 g_featsH[(size_t)NND * NFEAT], g_featsL[(size_t)NND * NFEAT];
__device__ bf16 g_W1TH[NHID * NFEAT],  g_W1TL[NHID * NFEAT];
__device__ bf16 g_WqTH[NHID * NHID],   g_WqTL[NHID * NHID];
__device__ bf16 g_WkTH[NHID * NHID],   g_WkTL[NHID * NHID];
__device__ bf16 g_WvTH[NHID * NHID],   g_WvTL[NHID * NHID];
__device__ bf16 g_fW1TH[(size_t)NHID * NND], g_fW1TL[(size_t)NHID * NND];
__device__ bf16 g_xH[(size_t)NND * NHID],  g_xL[(size_t)NND * NHID];
__device__ bf16 g_QH[(size_t)NND * NHID],  g_QL[(size_t)NND * NHID];
__device__ bf16 g_KHb[(size_t)NND * NHID], g_KLb[(size_t)NND * NHID];
__device__ bf16 g_VTH[(size_t)NHID * NND], g_VTL[(size_t)NHID * NND];

// ---------------- helpers ----------------
__device__ __forceinline__ uint32_t s2u(const void* p) {
    uint32_t a;
    asm("{ .reg .u64 t; cvta.to.shared.u64 t, %1; cvt.u32.u64 %0, t; }" : "=r"(a) : "l"(p));
    return a;
}
__device__ __forceinline__ void split1(float v, bf16& h, bf16& l) {
    h = __float2bfloat16(v);
    l = __float2bfloat16(v - __bfloat162float(h));
}
__device__ __forceinline__ void cvt_split2(float x, float y, uint32_t& hi, uint32_t& lo) {
    __nv_bfloat162 h = __float22bfloat162_rn(make_float2(x, y));
    hi = *reinterpret_cast<uint32_t*>(&h);
    float hx = __uint_as_float(hi << 16);
    float hy = __uint_as_float(hi & 0xFFFF0000u);
    __nv_bfloat162 l = __float22bfloat162_rn(make_float2(x - hx, y - hy));
    lo = *reinterpret_cast<uint32_t*>(&l);
}
__device__ __forceinline__ void split4(float4 v, uint2& h, uint2& l) {
    cvt_split2(v.x, v.y, h.x, l.x);
    cvt_split2(v.z, v.w, h.y, l.y);
}
__device__ __forceinline__ float2 bf2f2(uint32_t u) {
    return __bfloat1622float2(*reinterpret_cast<__nv_bfloat162*>(&u));
}

#define LDSM4(r, a)                                                                        \
    asm volatile("ldmatrix.sync.aligned.m8n8.x4.shared.b16 {%0,%1,%2,%3}, [%4];"           \
                 : "=r"((r)[0]), "=r"((r)[1]), "=r"((r)[2]), "=r"((r)[3]) : "r"(a))
#define LDSM2(r, a)                                                                        \
    asm volatile("ldmatrix.sync.aligned.m8n8.x2.shared.b16 {%0,%1}, [%2];"                 \
                 : "=r"((r)[0]), "=r"((r)[1]) : "r"(a))

__device__ __forceinline__ void mma16816(float c[4], const uint32_t a[4], const uint32_t b[2]) {
    asm volatile(
        "mma.sync.aligned.m16n8k16.row.col.f32.bf16.bf16.f32 "
        "{%0,%1,%2,%3}, {%4,%5,%6,%7}, {%8,%9}, {%0,%1,%2,%3};"
        : "+f"(c[0]), "+f"(c[1]), "+f"(c[2]), "+f"(c[3])
        : "r"(a[0]), "r"(a[1]), "r"(a[2]), "r"(a[3]), "r"(b[0]), "r"(b[1]));
}

// ---------------- GEMM: C = act((A @ B'^T) * mul + bias) ----------------
// Pre-split bf16 H/L operands. Tile 128 x BN, 512 threads / 16 warps (4x4 grid),
// warp tile 32 x (BN/4), KC=32/iter. 3-term split Ah*Bh + Ah*Bl + Al*Bh, fp32 acc.
struct GArgs {
    const bf16* AH[3]; const bf16* AL[3];
    const bf16* BH[3]; const bf16* BL[3];
    float* C[3];
    bf16* CH[3]; bf16* CL[3];
    const float* bias[3];
    const bf16* mulH; const bf16* mulL;   // optional elementwise mul (reconstruct H+L)
    int M, N, K, lda, ldb, ldc, act;
    int kLen;            // 0: bz = batch index; else bz = K-chunk index
    int estore[3];       // 0 fp32, 2 split, 3 split transposed (BN==128 only)
};

#define ROWB 80
#define ATILEB (128 * ROWB)

template <int BN>
__global__ void __launch_bounds__(512, 1) mma_gemm(const GArgs p) {
    constexpr int NT = BN / 32;              // n-tiles per warp
    constexpr int NBQ = BN / 128;            // B fill chunks per thread per tile
    constexpr int BTILEB = BN * ROWB;
    constexpr int STAGEB = 2 * ATILEB + 2 * BTILEB;
    extern __shared__ __align__(16) char smem[];

    const int bz = blockIdx.z;
    const int bi = p.kLen ? 0 : bz;
    const int kOff = p.kLen ? bz * p.kLen : 0;
    const int Kloc = p.kLen ? p.kLen : p.K;

    const int m0 = blockIdx.x * 128, n0 = blockIdx.y * BN;
    const int lda = p.lda, ldb = p.ldb, ldc = p.ldc;

    const bf16* __restrict__ pAH = p.AH[bi] + (size_t)m0 * lda + kOff;
    const bf16* __restrict__ pAL = p.AL[bi] + (size_t)m0 * lda + kOff;
    const bf16* __restrict__ pBH = p.BH[bi] + (size_t)n0 * ldb + kOff;
    const bf16* __restrict__ pBL = p.BL[bi] + (size_t)n0 * ldb + kOff;
    const float* __restrict__ bias = p.bias[bi];

    const int tid  = threadIdx.x;
    const int lane = tid & 31, wid = tid >> 5;
    const int wm = wid & 3, wn = wid >> 2;

    const uint32_t u0 = s2u(smem);
    const uint32_t aRowOff = (uint32_t)((lane & 15) * ROWB + ((lane & 16) ? 16 : 0));
    const uint32_t bRowOff = (uint32_t)((lane & 7) * ROWB + ((lane & 8) ? 16 : 0));

    float acc[2][NT][4];
#pragma unroll
    for (int mt = 0; mt < 2; mt++)
#pragma unroll
        for (int nt = 0; nt < NT; nt++)
#pragma unroll
            for (int q = 0; q < 4; q++) acc[mt][nt][q] = 0.f;

    uint4 rah, ral, rbh[NBQ], rbl[NBQ];
    const int fRow = tid >> 2;
    const int fC8  = (tid & 3) << 3;
    const int fOff = fRow * ROWB + ((tid & 3) << 4);

    auto loadT = [&](int k0) {
        rah = *reinterpret_cast<const uint4*>(pAH + (size_t)fRow * lda + k0 + fC8);
        ral = *reinterpret_cast<const uint4*>(pAL + (size_t)fRow * lda + k0 + fC8);
#pragma unroll
        for (int q = 0; q < NBQ; q++) {
            int row = fRow + q * 128;
            rbh[q] = *reinterpret_cast<const uint4*>(pBH + (size_t)row * ldb + k0 + fC8);
            rbl[q] = *reinterpret_cast<const uint4*>(pBL + (size_t)row * ldb + k0 + fC8);
        }
    };
    auto storeT = [&](int stage) {
        char* AHs = smem + stage * STAGEB;
        char* ALs = AHs + ATILEB;
        char* BHs = ALs + ATILEB;
        char* BLs = BHs + BTILEB;
        *reinterpret_cast<uint4*>(AHs + fOff) = rah;
        *reinterpret_cast<uint4*>(ALs + fOff) = ral;
#pragma unroll
        for (int q = 0; q < NBQ; q++) {
            *reinterpret_cast<uint4*>(BHs + fOff + q * 128 * ROWB) = rbh[q];
            *reinterpret_cast<uint4*>(BLs + fOff + q * 128 * ROWB) = rbl[q];
        }
    };
    auto compute = [&](int stage) {
        const uint32_t uAH = u0 + (uint32_t)(stage * STAGEB);
        const uint32_t uAL = uAH + ATILEB;
        const uint32_t uBH = uAL + ATILEB;
        const uint32_t uBL = uBH + BTILEB;
#pragma unroll
        for (int ks = 0; ks < 2; ks++) {
            const uint32_t ka = (uint32_t)(ks * 32);
            uint32_t ah[2][4], bh[NT][2];
#pragma unroll
            for (int mt = 0; mt < 2; mt++)
                LDSM4(ah[mt], uAH + (uint32_t)((wm * 32 + mt * 16) * ROWB) + aRowOff + ka);
#pragma unroll
            for (int nt = 0; nt < NT; nt++)
                LDSM2(bh[nt], uBH + (uint32_t)((wn * (NT * 8) + nt * 8) * ROWB) + bRowOff + ka);
#pragma unroll
            for (int mt = 0; mt < 2; mt++)
#pragma unroll
                for (int nt = 0; nt < NT; nt++) mma16816(acc[mt][nt], ah[mt], bh[nt]);
            // pass 2: Ah * Bl, bl loaded on the fly (short live range)
#pragma unroll
            for (int nt = 0; nt < NT; nt++) {
                uint32_t bl2[2];
                LDSM2(bl2, uBL + (uint32_t)((wn * (NT * 8) + nt * 8) * ROWB) + bRowOff + ka);
#pragma unroll
                for (int mt = 0; mt < 2; mt++) mma16816(acc[mt][nt], ah[mt], bl2);
            }
            // pass 3: Al * Bh
#pragma unroll
            for (int mt = 0; mt < 2; mt++) {
                uint32_t alf[4];
                LDSM4(alf, uAL + (uint32_t)((wm * 32 + mt * 16) * ROWB) + aRowOff + ka);
#pragma unroll
                for (int nt = 0; nt < NT; nt++) mma16816(acc[mt][nt], alf, bh[nt]);
            }
        }
    };

    const int niter = Kloc >> 5;
    loadT(0);
    storeT(0);
    if (niter > 1) loadT(32);
    __syncthreads();
    for (int i = 0; i < niter; i++) {
        if (i + 1 < niter) storeT((i + 1) & 1);
        if (i + 2 < niter) loadT((i + 2) << 5);
        compute(i & 1);
        __syncthreads();
    }

    // ---------------- epilogue ----------------
    const int es = p.estore[bz];
    float* __restrict__ C  = p.C[bz];
    bf16* __restrict__ CH = p.CH[bz];
    bf16* __restrict__ CL = p.CL[bz];

    if (es == 3) {
        // transposed split store, staged through smem for coalescing (BN==128 path)
        bf16* sH = reinterpret_cast<bf16*>(smem);
        bf16* sL = reinterpret_cast<bf16*>(smem + BN * 128 * 2);
#pragma unroll
        for (int mt = 0; mt < 2; mt++)
#pragma unroll
            for (int nt = 0; nt < NT; nt++) {
                int ml = wm * 32 + mt * 16 + (lane >> 2);
                int nl = wn * (NT * 8) + nt * 8 + 2 * (lane & 3);
#pragma unroll
                for (int h = 0; h < 2; h++) {
                    int mm = ml + h * 8;
                    float vx = acc[mt][nt][2 * h + 0];
                    float vy = acc[mt][nt][2 * h + 1];
                    if (bias) { vx += bias[n0 + nl]; vy += bias[n0 + nl + 1]; }
                    if (p.act) { vx = fmaxf(vx, 0.f); vy = fmaxf(vy, 0.f); }
                    bf16 hx, lx, hy, ly;
                    split1(vx, hx, lx);
                    split1(vy, hy, ly);
                    sH[nl * 128 + mm] = hx;       sL[nl * 128 + mm] = lx;
                    sH[(nl + 1) * 128 + mm] = hy; sL[(nl + 1) * 128 + mm] = ly;
                }
            }
        __syncthreads();
        // 16B-coalesced writes: BN rows x 128 m
        const int nchunks = BN * 128 / 8;   // 8 bf16 per 16B chunk
        for (int idx = tid; idx < nchunks; idx += 512) {
            int nrow = idx >> 4;
            int seg  = (idx & 15) * 8;
            *reinterpret_cast<uint4*>(&CH[(size_t)(n0 + nrow) * p.M + m0 + seg]) =
                *reinterpret_cast<uint4*>(&sH[nrow * 128 + seg]);
            *reinterpret_cast<uint4*>(&CL[(size_t)(n0 + nrow) * p.M + m0 + seg]) =
                *reinterpret_cast<uint4*>(&sL[nrow * 128 + seg]);
        }
        return;
    }

    const bf16* __restrict__ mulH = p.mulH;
    const bf16* __restrict__ mulL = p.mulL;
#pragma unroll
    for (int mt = 0; mt < 2; mt++) {
#pragma unroll
        for (int nt = 0; nt < NT; nt++) {
            int mA = m0 + wm * 32 + mt * 16 + (lane >> 2);
            int n  = n0 + wn * (NT * 8) + nt * 8 + 2 * (lane & 3);
#pragma unroll
            for (int h = 0; h < 2; h++) {
                int mm = mA + h * 8;
                float vx = acc[mt][nt][2 * h + 0];
                float vy = acc[mt][nt][2 * h + 1];
                if (mulH) {
                    float2 mh = bf2f2(*reinterpret_cast<const uint32_t*>(&mulH[(size_t)mm * ldc + n]));
                    float2 ml = bf2f2(*reinterpret_cast<const uint32_t*>(&mulL[(size_t)mm * ldc + n]));
                    vx *= (mh.x + ml.x); vy *= (mh.y + ml.y);
                }
                if (bias) { vx += bias[n]; vy += bias[n + 1]; }
                if (p.act) { vx = fmaxf(vx, 0.f); vy = fmaxf(vy, 0.f); }
                if (es == 0) {
                    *reinterpret_cast<float2*>(&C[(size_t)mm * ldc + n]) = make_float2(vx, vy);
                } else {  // es == 2: split, row-major
                    uint32_t hi, lo;
                    cvt_split2(vx, vy, hi, lo);
                    *reinterpret_cast<uint32_t*>(&CH[(size_t)mm * ldc + n]) = hi;
                    *reinterpret_cast<uint32_t*>(&CL[(size_t)mm * ldc + n]) = lo;
                }
            }
        }
    }
}

// ---- split-K reduce: x = relu(sum part + bias) -> bf16 H/L ----
__global__ void reduce_split_k(const float* __restrict__ bias, bf16* __restrict__ oH,
                               bf16* __restrict__ oL) {
    const int n4 = NND * NHID / 4;
    const size_t S = (size_t)NND * NHID;
    for (int e = blockIdx.x * blockDim.x + threadIdx.x; e < n4; e += gridDim.x * blockDim.x) {
        float4 a = reinterpret_cast<const float4*>(g_part)[e];
        float4 b = reinterpret_cast<const float4*>(g_part + S)[e];
        float4 c = reinterpret_cast<const float4*>(g_part + 2 * S)[e];
        int col = (e * 4) & (NHID - 1);
        float4 v;
        v.x = fmaxf(a.x + b.x + c.x + bias[col + 0], 0.f);
        v.y = fmaxf(a.y + b.y + c.y + bias[col + 1], 0.f);
        v.z = fmaxf(a.z + b.z + c.z + bias[col + 2], 0.f);
        v.w = fmaxf(a.w + b.w + c.w + bias[col + 3], 0.f);
        uint2 h, l;
        split4(v, h, l);
        reinterpret_cast<uint2*>(oH)[e] = h;
        reinterpret_cast<uint2*>(oL)[e] = l;
    }
}
// ---- split-K reduce: xt = relu(sum part) -> fp32 ----
__global__ void reduce_f32_k(float* __restrict__ o) {
    const int n4 = NND * NHID / 4;
    const size_t S = (size_t)NND * NHID;
    for (int e = blockIdx.x * blockDim.x + threadIdx.x; e < n4; e += gridDim.x * blockDim.x) {
        float4 a = reinterpret_cast<const float4*>(g_part)[e];
        float4 b = reinterpret_cast<const float4*>(g_part + S)[e];
        float4 c = reinterpret_cast<const float4*>(g_part + 2 * S)[e];
        float4 v;
        v.x = fmaxf(a.x + b.x + c.x, 0.f);
        v.y = fmaxf(a.y + b.y + c.y, 0.f);
        v.z = fmaxf(a.z + b.z + c.z, 0.f);
        v.w = fmaxf(a.w + b.w + c.w, 0.f);
        reinterpret_cast<float4*>(o)[e] = v;
    }
}

// ---------------- transpose + split ----------------
struct TSArgs {
    const float* in[3];
    bf16* oH[3]; bf16* oL[3];
    int R, C;
};
__global__ void transpose_split_k(const TSArgs p) {
    __shared__ float t[32][33];
    const float* __restrict__ in = p.in[blockIdx.z];
    bf16* __restrict__ oH = p.oH[blockIdx.z];
    bf16* __restrict__ oL = p.oL[blockIdx.z];
    const int R = p.R, C = p.C;
    int c0 = blockIdx.x * 32, r0 = blockIdx.y * 32;
    int x = threadIdx.x, y = threadIdx.y;
#pragma unroll
    for (int i = 0; i < 32; i += 8) t[y + i][x] = in[(size_t)(r0 + y + i) * C + c0 + x];
    __syncthreads();
#pragma unroll
    for (int i = 0; i < 32; i += 8) {
        float v = t[x][y + i];
        bf16 h, l;
        split1(v, h, l);
        oH[(size_t)(c0 + y + i) * R + r0 + x] = h;
        oL[(size_t)(c0 + y + i) * R + r0 + x] = l;
    }
}

// ---------------- elementwise split ----------------
__global__ void split_k(const float* __restrict__ in, bf16* __restrict__ oH,
                        bf16* __restrict__ oL, int n4) {
    for (int e = blockIdx.x * blockDim.x + threadIdx.x; e < n4; e += gridDim.x * blockDim.x) {
        float4 v = reinterpret_cast<const float4*>(in)[e];
        uint2 h, l;
        split4(v, h, l);
        reinterpret_cast<uint2*>(oH)[e] = h;
        reinterpret_cast<uint2*>(oL)[e] = l;
    }
}

// ---- fold: Wfold[l][j][c] = sum_k Wa_l[j,k] * Wagg[l*128+k, c]; bfold = ba@Wagg+bagg
__global__ void fold_k(const float* __restrict__ Wa1, const float* __restrict__ Wa2,
                       const float* __restrict__ Wa3, const float* __restrict__ Wagg,
                       const float* __restrict__ bagg, const float* __restrict__ ba1,
                       const float* __restrict__ ba2, const float* __restrict__ ba3) {
    int j = blockIdx.x * 128 + threadIdx.x;
    int l = blockIdx.y;
    const float* Wa = (l == 0) ? Wa1 : (l == 1) ? Wa2 : Wa3;
    float c0 = 0.f, c1 = 0.f, c2 = 0.f;
    for (int k = 0; k < ADIM; k++) {
        float a = Wa[(size_t)j * ADIM + k];
        const float* wg = &Wagg[(l * ADIM + k) * 3];
        c0 = fmaf(a, wg[0], c0);
        c1 = fmaf(a, wg[1], c1);
        c2 = fmaf(a, wg[2], c2);
    }
    // SoA layout: g_wfold[(l*3+c)*NND + j]
    g_wfold[(l * 3 + 0) * NND + j] = c0;
    g_wfold[(l * 3 + 1) * NND + j] = c1;
    g_wfold[(l * 3 + 2) * NND + j] = c2;
    if (blockIdx.x == 0 && l == 0 && threadIdx.x < 3) {
        int c = threadIdx.x;
        float b = bagg[c];
        for (int k = 0; k < ADIM; k++) {
            b += ba1[k] * Wagg[k * 3 + c];
            b += ba2[k] * Wagg[(ADIM + k) * 3 + c];
            b += ba3[k] * Wagg[(2 * ADIM + k) * 3 + c];
        }
        g_bfold[c] = b;
    }
}

// ---- gemv+gate: z4[r,c] = sum_l sum_j adj_l[r,j]*Wfold[l][j][c] + bfold; nz=softmax
#define GV_ROWS 32
#define GV_CH 512
__device__ __forceinline__ float dot4(float4 a, float4 b) {
    return a.x * b.x + a.y * b.y + a.z * b.z + a.w * b.w;
}
__global__ void gemv_nz_k(const float* __restrict__ a0, const float* __restrict__ a1,
                          const float* __restrict__ a2, float* __restrict__ out_nz,
                          int write_out) {
    __shared__ float sw[9][GV_CH];
    const int tid = threadIdx.x;
    const int lane = tid & 31, warp = tid >> 5;
    const int rbase = blockIdx.x * GV_ROWS + warp * 4;
    float s[4][3];
#pragma unroll
    for (int r = 0; r < 4; r++)
#pragma unroll
        for (int c = 0; c < 3; c++) s[r][c] = 0.f;

    for (int ch = 0; ch < NND; ch += GV_CH) {
        __syncthreads();
        for (int idx = tid; idx < 9 * GV_CH; idx += 256) {
            int t = idx / GV_CH, j = idx % GV_CH;   // t = l*3+c
            sw[t][j] = g_wfold[(size_t)t * NND + ch + j];
        }
        __syncthreads();
#pragma unroll 2
        for (int j = lane * 4; j < GV_CH; j += 128) {
            float4 wv[9];
#pragma unroll
            for (int t = 0; t < 9; t++) wv[t] = *reinterpret_cast<const float4*>(&sw[t][j]);
#pragma unroll
            for (int r = 0; r < 4; r++) {
                size_t off = (size_t)(rbase + r) * NND + ch + j;
                float4 v0 = *reinterpret_cast<const float4*>(a0 + off);
                float4 v1 = *reinterpret_cast<const float4*>(a1 + off);
                float4 v2 = *reinterpret_cast<const float4*>(a2 + off);
                s[r][0] += dot4(v0, wv[0]) + dot4(v1, wv[3]) + dot4(v2, wv[6]);
                s[r][1] += dot4(v0, wv[1]) + dot4(v1, wv[4]) + dot4(v2, wv[7]);
                s[r][2] += dot4(v0, wv[2]) + dot4(v1, wv[5]) + dot4(v2, wv[8]);
            }
        }
    }
#pragma unroll
    for (int r = 0; r < 4; r++)
#pragma unroll
        for (int c = 0; c < 3; c++) {
            float v = s[r][c];
#pragma unroll
            for (int off = 16; off; off >>= 1) v += __shfl_down_sync(0xffffffffu, v, off);
            s[r][c] = v;
        }
    if (lane == 0) {
#pragma unroll
        for (int r = 0; r < 4; r++) {
            int row = rbase + r;
            float z0 = s[r][0] + g_bfold[0];
            float z1 = s[r][1] + g_bfold[1];
            float z2 = s[r][2] + g_bfold[2];
            float mx = fmaxf(z0, fmaxf(z1, z2));
            float e0 = expf(z0 - mx), e1 = expf(z1 - mx), e2 = expf(z2 - mx);
            float inv = 1.f / (e0 + e1 + e2);
            e0 *= inv; e1 *= inv; e2 *= inv;
            g_nzT[0 * NND + row] = e0;
            g_nzT[1 * NND + row] = e1;
            g_nzT[2 * NND + row] = e2;
            if (write_out) {
                out_nz[row * 3 + 0] = e0;
                out_nz[row * 3 + 1] = e1;
                out_nz[row * 3 + 2] = e2;
            }
        }
    }
}

// ---- adj = col-weighted mix; emit bf16 H/L only (no fp32), 8 elems/iter ----
__global__ void build_adj_k(const float* __restrict__ a0, const float* __restrict__ a1,
                            const float* __restrict__ a2) {
    const size_t total8 = (size_t)NND * NND / 8;
    for (size_t e = (size_t)blockIdx.x * blockDim.x + threadIdx.x; e < total8;
         e += (size_t)gridDim.x * blockDim.x) {
        size_t off = e * 8;
        int j = (int)(off % NND);
#pragma unroll
        for (int u = 0; u < 2; u++) {
            size_t o = off + u * 4;
            int jj = j + u * 4;
            float4 w0 = *reinterpret_cast<const float4*>(&g_nzT[jj]);
            float4 w1 = *reinterpret_cast<const float4*>(&g_nzT[NND + jj]);
            float4 w2 = *reinterpret_cast<const float4*>(&g_nzT[2 * NND + jj]);
            float4 x0 = *reinterpret_cast<const float4*>(a0 + o);
            float4 x1 = *reinterpret_cast<const float4*>(a1 + o);
            float4 x2 = *reinterpret_cast<const float4*>(a2 + o);
            float4 r;
            r.x = w0.x * x0.x + w1.x * x1.x + w2.x * x2.x;
            r.y = w0.y * x0.y + w1.y * x1.y + w2.y * x2.y;
            r.z = w0.z * x0.z + w1.z * x1.z + w2.z * x2.z;
            r.w = w0.w * x0.w + w1.w * x1.w + w2.w * x2.w;
            uint2 h, l;
            split4(r, h, l);
            *reinterpret_cast<uint2*>(&g_adjH[o]) = h;
            *reinterpret_cast<uint2*>(&g_adjL[o]) = l;
        }
    }
}

// ---- per-row softmax over 6144-wide fp32 logits; emit bf16 split ----
__global__ void attn_softmax_k() {
    const int row = blockIdx.x;
    const float* __restrict__ ptr = &g_att[(size_t)row * NND];
    const int tid  = threadIdx.x;
    const int lane = tid & 31, warp = tid >> 5;
    float4 v[6];
    float mx = -3.4e38f;
#pragma unroll
    for (int l = 0; l < 6; l++) {
        v[l] = *reinterpret_cast<const float4*>(&ptr[(tid + l * 256) * 4]);
        mx = fmaxf(mx, fmaxf(fmaxf(v[l].x, v[l].y), fmaxf(v[l].z, v[l].w)));
    }
    __shared__ float sm[8], ss[8];
#pragma unroll
    for (int off = 16; off; off >>= 1) mx = fmaxf(mx, __shfl_xor_sync(0xffffffffu, mx, off));
    if (lane == 0) sm[warp] = mx;
    __syncthreads();
    float bm = fmaxf(fmaxf(fmaxf(sm[0], sm[1]), fmaxf(sm[2], sm[3])),
                     fmaxf(fmaxf(sm[4], sm[5]), fmaxf(sm[6], sm[7])));
    float sum = 0.f;
#pragma unroll
    for (int l = 0; l < 6; l++) {
        v[l].x = expf(v[l].x - bm);
        v[l].y = expf(v[l].y - bm);
        v[l].z = expf(v[l].z - bm);
        v[l].w = expf(v[l].w - bm);
        sum += v[l].x + v[l].y + v[l].z + v[l].w;
    }
#pragma unroll
    for (int off = 16; off; off >>= 1) sum += __shfl_xor_sync(0xffffffffu, sum, off);
    if (lane == 0) ss[warp] = sum;
    __syncthreads();
    float tot = ss[0] + ss[1] + ss[2] + ss[3] + ss[4] + ss[5] + ss[6] + ss[7];
    float scale = 1.f / tot;
#pragma unroll
    for (int l = 0; l < 6; l++) {
        v[l].x *= scale; v[l].y *= scale; v[l].z *= scale; v[l].w *= scale;
        uint2 h, lo;
        split4(v[l], h, lo);
        size_t off = (size_t)row * NND + (tid + l * 256) * 4;
        *reinterpret_cast<uint2*>(&g_attH[off]) = h;
        *reinterpret_cast<uint2*>(&g_attL[off]) = lo;
    }
}

// ---------------- X_tilde @ W2 (skinny, N=8) ----------------
__global__ void xtw2_k(const float* __restrict__ W2) {
    int row  = blockIdx.x * 8 + (threadIdx.x >> 5);
    int lane = threadIdx.x & 31;
    if (row >= NND) return;
    const float* xr = &g_xt[(size_t)row * NHID];
    float acc[8] = {0, 0, 0, 0, 0, 0, 0, 0};
    for (int h = lane; h < NHID; h += 32) {
        float xv = xr[h];
        const float4* wp = reinterpret_cast<const float4*>(&W2[h * 8]);
        float4 wlo = wp[0], whi = wp[1];
        acc[0] = fmaf(xv, wlo.x, acc[0]);
        acc[1] = fmaf(xv, wlo.y, acc[1]);
        acc[2] = fmaf(xv, wlo.z, acc[2]);
        acc[3] = fmaf(xv, wlo.w, acc[3]);
        acc[4] = fmaf(xv, whi.x, acc[4]);
        acc[5] = fmaf(xv, whi.y, acc[5]);
        acc[6] = fmaf(xv, whi.z, acc[6]);
        acc[7] = fmaf(xv, whi.w, acc[7]);
    }
#pragma unroll
    for (int c = 0; c < 8; c++)
#pragma unroll
        for (int off = 16; off; off >>= 1) acc[c] += __shfl_down_sync(0xffffffffu, acc[c], off);
    if (lane == 0) {
#pragma unroll
        for (int c = 0; c < 8; c++) g_xtw2[row * 8 + c] = acc[c];
    }
}

// ---------------- z = (adjH+adjL) @ xtw2 + b2 ; out = softmax(z). 8 rows/CTA ----
__global__ void final_k(const float* __restrict__ b2, float* __restrict__ out) {
    const int r0  = blockIdx.x * 8;
    const int tid = threadIdx.x;
    float acc[8][8];
#pragma unroll
    for (int r = 0; r < 8; r++)
#pragma unroll
        for (int c = 0; c < 8; c++) acc[r][c] = 0.f;

    for (int j4 = tid; j4 < NND / 4; j4 += 256) {
        float4 w[8];
        const float4* wp = reinterpret_cast<const float4*>(&g_xtw2[(size_t)j4 * 32]);
#pragma unroll
        for (int q = 0; q < 8; q++) w[q] = wp[q];
#pragma unroll
        for (int r = 0; r < 8; r++) {
            size_t off = (size_t)(r0 + r) * NND + j4 * 4;
            uint2 hz = *reinterpret_cast<const uint2*>(&g_adjH[off]);
            uint2 lz = *reinterpret_cast<const uint2*>(&g_adjL[off]);
            float2 h0 = bf2f2(hz.x), h1 = bf2f2(hz.y);
            float2 l0 = bf2f2(lz.x), l1 = bf2f2(lz.y);
            float av[4] = {h0.x + l0.x, h0.y + l0.y, h1.x + l1.x, h1.y + l1.y};
#pragma unroll
            for (int q = 0; q < 4; q++) {
                acc[r][0] = fmaf(av[q], w[2 * q].x, acc[r][0]);
                acc[r][1] = fmaf(av[q], w[2 * q].y, acc[r][1]);
                acc[r][2] = fmaf(av[q], w[2 * q].z, acc[r][2]);
                acc[r][3] = fmaf(av[q], w[2 * q].w, acc[r][3]);
                acc[r][4] = fmaf(av[q], w[2 * q + 1].x, acc[r][4]);
                acc[r][5] = fmaf(av[q], w[2 * q + 1].y, acc[r][5]);
                acc[r][6] = fmaf(av[q], w[2 * q + 1].z, acc[r][6]);
                acc[r][7] = fmaf(av[q], w[2 * q + 1].w, acc[r][7]);
            }
        }
    }

    __shared__ float sred[8][64];
    const int lane = tid & 31, warp = tid >> 5;
#pragma unroll
    for (int r = 0; r < 8; r++)
#pragma unroll
        for (int c = 0; c < 8; c++) {
            float vv = acc[r][c];
#pragma unroll
            for (int off = 16; off; off >>= 1) vv += __shfl_down_sync(0xffffffffu, vv, off);
            if (lane == 0) sred[warp][r * 8 + c] = vv;
        }
    __syncthreads();
    if (tid < 64) {
        float v = 0.f;
#pragma unroll
        for (int w = 0; w < 8; w++) v += sred[w][tid];
        int c = tid & 7;
        v += b2[c];
        float mx = v;
#pragma unroll
        for (int off = 4; off; off >>= 1) mx = fmaxf(mx, __shfl_xor_sync(0xffffffffu, mx, off, 8));
        float e = expf(v - mx);
        float s = e;
#pragma unroll
        for (int off = 4; off; off >>= 1) s += __shfl_xor_sync(0xffffffffu, s, off, 8);
        out[(size_t)(r0 + (tid >> 3)) * 8 + c] = e / s;
    }
}

// ---------------- host side ----------------
template <typename T>
static T* symaddr(const void* sym) {
    void* p = nullptr;
    cudaGetSymbolAddress(&p, sym);
    return (T*)p;
}

#define GSMEM128 (2 * (2 * ATILEB + 2 * 128 * ROWB))   // 81920
#define GSMEM256 (2 * (2 * ATILEB + 2 * 256 * ROWB))   // 122880

extern "C" void kernel_launch(void* const* d_in, const int* in_sizes, int n_in,
                              void* d_out, int out_size) {
    const float* adj0 = (const float*)d_in[0];
    const float* adj1 = (const float*)d_in[1];
    const float* adj2 = (const float*)d_in[2];
    const float* feats = (const float*)d_in[3];
    const float* Wa1 = (const float*)d_in[4];
    const float* ba1 = (const float*)d_in[5];
    const float* Wa2 = (const float*)d_in[6];
    const float* ba2 = (const float*)d_in[7];
    const float* Wa3 = (const float*)d_in[8];
    const float* ba3 = (const float*)d_in[9];
    const float* Wagg = (const float*)d_in[10];
    const float* bagg = (const float*)d_in[11];
    const float* W1 = (const float*)d_in[12];
    const float* b1 = (const float*)d_in[13];
    const float* Wq = (const float*)d_in[14];
    const float* bq = (const float*)d_in[15];
    const float* Wk = (const float*)d_in[16];
    const float* bk = (const float*)d_in[17];
    const float* Wv = (const float*)d_in[18];
    const float* bv = (const float*)d_in[19];
    const float* W2 = (const float*)d_in[20];
    const float* b2 = (const float*)d_in[21];
    float* out = (float*)d_out;

    float* attp  = symaddr<float>(g_att);
    float* partp = symaddr<float>(g_part);
    float* xtp   = symaddr<float>(g_xt);
    bf16* adjH = symaddr<bf16>(g_adjH);   bf16* adjL = symaddr<bf16>(g_adjL);
    bf16* attH = symaddr<bf16>(g_attH);   bf16* attL = symaddr<bf16>(g_attL);
    bf16* ftH  = symaddr<bf16>(g_featsH); bf16* ftL  = symaddr<bf16>(g_featsL);
    bf16* W1TH = symaddr<bf16>(g_W1TH);   bf16* W1TL = symaddr<bf16>(g_W1TL);
    bf16* WqTH = symaddr<bf16>(g_WqTH);   bf16* WqTL = symaddr<bf16>(g_WqTL);
    bf16* WkTH = symaddr<bf16>(g_WkTH);   bf16* WkTL = symaddr<bf16>(g_WkTL);
    bf16* WvTH = symaddr<bf16>(g_WvTH);   bf16* WvTL = symaddr<bf16>(g_WvTL);
    bf16* fW1TH = symaddr<bf16>(g_fW1TH); bf16* fW1TL = symaddr<bf16>(g_fW1TL);
    bf16* xH   = symaddr<bf16>(g_xH);     bf16* xL   = symaddr<bf16>(g_xL);
    bf16* QH   = symaddr<bf16>(g_QH);     bf16* QL   = symaddr<bf16>(g_QL);
    bf16* KHp  = symaddr<bf16>(g_KHb);    bf16* KLp  = symaddr<bf16>(g_KLb);
    bf16* VTH  = symaddr<bf16>(g_VTH);    bf16* VTL  = symaddr<bf16>(g_VTL);

    cudaFuncSetAttribute(mma_gemm<128>, cudaFuncAttributeMaxDynamicSharedMemorySize, GSMEM128);
    cudaFuncSetAttribute(mma_gemm<256>, cudaFuncAttributeMaxDynamicSharedMemorySize, GSMEM256);

    int write_nz = (out_size >= NND * (NCLASS + 3)) ? 1 : 0;
    const size_t PS = (size_t)NND * NHID;

    // 0: feats split
    split_k<<<592, 256>>>(feats, ftH, ftL, NND * NFEAT / 4);
    // 1: W1 transpose+split
    {
        TSArgs t{};
        t.in[0] = W1; t.oH[0] = W1TH; t.oL[0] = W1TL; t.R = NFEAT; t.C = NHID;
        transpose_split_k<<<dim3(NHID / 32, NFEAT / 32, 1), dim3(32, 8)>>>(t);
    }
    // 2: fold
    fold_k<<<dim3(NND / 128, 3), 128>>>(Wa1, Wa2, Wa3, Wagg, bagg, ba1, ba2, ba3);

    // 3: L4: fW1^T(split) = (feats @ W1)^T   <-- profiled launch
    {
        GArgs a{};
        a.AH[0] = ftH; a.AL[0] = ftL;
        a.BH[0] = W1TH; a.BL[0] = W1TL;
        a.CH[0] = fW1TH; a.CL[0] = fW1TL;
        a.M = NND; a.N = NHID; a.K = NFEAT; a.lda = NFEAT; a.ldb = NFEAT; a.ldc = NHID;
        a.estore[0] = 3;
        mma_gemm<128><<<dim3(48, 2, 1), 512, GSMEM128>>>(a);
    }

    // 4: gemv + gate softmax -> nz
    gemv_nz_k<<<NND / GV_ROWS, 256>>>(adj0, adj1, adj2, out + (size_t)NND * NCLASS, write_nz);
    // 5: Wq/Wk/Wv transpose+split (batched)
    {
        TSArgs t{};
        t.in[0] = Wq; t.in[1] = Wk; t.in[2] = Wv;
        t.oH[0] = WqTH; t.oH[1] = WkTH; t.oH[2] = WvTH;
        t.oL[0] = WqTL; t.oL[1] = WkTL; t.oL[2] = WvTL;
        t.R = NHID; t.C = NHID;
        transpose_split_k<<<dim3(NHID / 32, NHID / 32, 3), dim3(32, 8)>>>(t);
    }
    // 6: fused adjacency (bf16 H/L only)
    build_adj_k<<<1184, 256>>>(adj0, adj1, adj2);

    // 7: L5 split-K (BN=256, single y-block -> A read once)
    {
        GArgs a{};
        a.AH[0] = adjH; a.AL[0] = adjL;
        a.BH[0] = fW1TH; a.BL[0] = fW1TL;
        a.C[0] = partp; a.C[1] = partp + PS; a.C[2] = partp + 2 * PS;
        a.M = NND; a.N = NHID; a.K = NND; a.lda = NND; a.ldb = NND; a.ldc = NHID;
        a.kLen = NND / 3;
        a.estore[0] = a.estore[1] = a.estore[2] = 0;
        mma_gemm<256><<<dim3(48, 1, 3), 512, GSMEM256>>>(a);
    }
    // 8: reduce -> x (split)
    reduce_split_k<<<1536, 256>>>(b1, xH, xL);

    // 9: L6: Q,K (split); V (split transposed, staged)
    {
        GArgs a{};
        a.AH[0] = a.AH[1] = a.AH[2] = xH;
        a.AL[0] = a.AL[1] = a.AL[2] = xL;
        a.BH[0] = WqTH; a.BH[1] = WkTH; a.BH[2] = WvTH;
        a.BL[0] = WqTL; a.BL[1] = WkTL; a.BL[2] = WvTL;
        a.CH[0] = QH; a.CL[0] = QL;
        a.CH[1] = KHp; a.CL[1] = KLp;
        a.CH[2] = VTH; a.CL[2] = VTL;
        a.bias[0] = bq; a.bias[1] = bk; a.bias[2] = bv;
        a.M = NND; a.N = NHID; a.K = NHID; a.lda = NHID; a.ldb = NHID; a.ldc = NHID;
        a.estore[0] = 2; a.estore[1] = 2; a.estore[2] = 3;
        mma_gemm<128><<<dim3(48, 2, 3), 512, GSMEM128>>>(a);
    }

    // 10: L7: A_tilde = (adjH+adjL) * (Q @ K^T)  (fp32 logits)
    {
        GArgs a{};
        a.AH[0] = QH; a.AL[0] = QL;
        a.BH[0] = KHp; a.BL[0] = KLp;
        a.C[0] = attp;
        a.mulH = adjH; a.mulL = adjL;
        a.M = NND; a.N = NND; a.K = NHID; a.lda = NHID; a.ldb = NHID; a.ldc = NND;
        a.estore[0] = 0;
        mma_gemm<128><<<dim3(48, 48, 1), 512, GSMEM128>>>(a);
    }

    // 11: row softmax -> att split
    attn_softmax_k<<<NND, 256>>>();

    // 12: L9 split-K (BN=256)
    {
        GArgs a{};
        a.AH[0] = attH; a.AL[0] = attL;
        a.BH[0] = VTH; a.BL[0] = VTL;
        a.C[0] = partp; a.C[1] = partp + PS; a.C[2] = partp + 2 * PS;
        a.M = NND; a.N = NHID; a.K = NND; a.lda = NND; a.ldb = NND; a.ldc = NHID;
        a.kLen = NND / 3;
        a.estore[0] = a.estore[1] = a.estore[2] = 0;
        mma_gemm<256><<<dim3(48, 1, 3), 512, GSMEM256>>>(a);
    }
    // 13: reduce -> xt (fp32, relu)
    reduce_f32_k<<<1536, 256>>>(xtp);

    // 14, 15
    xtw2_k<<<768, 256>>>(W2);
    final_k<<<768, 256>>>(b2, out);
}